// round 12
// baseline (speedup 1.0000x reference)
#include <cuda_runtime.h>
#include <cuda_fp16.h>
#include <math.h>
#include <stdint.h>

// Problem constants
#define BATCH 2
#define SEQ   2048
#define DMODEL 1024
#define NHEAD 16
#define DK    64
#define DFF   4096
#define MTOK  (BATCH * SEQ)           // 4096 tokens
#define QKV_LD 3072
#define LN_EPS 1e-5f

// ---------------- scratch (device globals; no allocation allowed) ----------
__device__ __half g_xn  [(size_t)MTOK * DMODEL];    // fp16 LN out
__device__ __half g_qkv [(size_t)MTOK * QKV_LD];    // fp16 q(pre-scaled),k
__device__ __half g_vT  [(size_t)MTOK * DMODEL];    // fp16 V transposed [b,h,d][s]
__device__ __half g_attn[(size_t)MTOK * DMODEL];    // fp16 attn out
__device__ float  g_x1  [(size_t)MTOK * DMODEL];    // fp32 residual-1
__device__ __half g_ff  [(size_t)MTOK * DFF];       // fp16 relu out
__device__ __half g_wqkv[(size_t)QKV_LD * DMODEL];  // fp16 weights
__device__ __half g_wo_h[(size_t)DMODEL * DMODEL];
__device__ __half g_w1_h[(size_t)DFF * DMODEL];
__device__ __half g_w2_h[(size_t)DMODEL * DFF];
__device__ float  g_bqkv[QKV_LD];

// ============================ helpers ======================================
__device__ __forceinline__ uint32_t smem_u32(const void* p) {
    uint32_t a;
    asm("{ .reg .u64 t; cvta.to.shared.u64 t, %1; cvt.u32.u64 %0, t; }"
        : "=r"(a) : "l"(p));
    return a;
}

__device__ __forceinline__ uint32_t f22h2(float a, float b) {
    __half2 h = __floats2half2_rn(a, b);
    return *reinterpret_cast<uint32_t*>(&h);
}

__device__ __forceinline__ void mma_f16(float* c, const uint32_t* a, const uint32_t* b) {
    asm volatile(
        "mma.sync.aligned.m16n8k16.row.col.f32.f16.f16.f32 "
        "{%0,%1,%2,%3}, {%4,%5,%6,%7}, {%8,%9}, {%0,%1,%2,%3};"
        : "+f"(c[0]), "+f"(c[1]), "+f"(c[2]), "+f"(c[3])
        : "r"(a[0]), "r"(a[1]), "r"(a[2]), "r"(a[3]),
          "r"(b[0]), "r"(b[1]));
}

#define LDSM_X4(r0, r1, r2, r3, addr) \
    asm volatile("ldmatrix.sync.aligned.m8n8.x4.shared.b16 {%0,%1,%2,%3}, [%4];" \
        : "=r"(r0), "=r"(r1), "=r"(r2), "=r"(r3) : "r"(addr))

#define CP_ASYNC16(dst, src) \
    asm volatile("cp.async.cg.shared.global [%0], [%1], 16;" :: \
        "r"(dst), "l"(src) : "memory")
#define CP_COMMIT() asm volatile("cp.async.commit_group;" ::: "memory")
#define CP_WAIT(n)  asm volatile("cp.async.wait_group %0;" :: "n"(n) : "memory")

// ---------------------------------------------------------------------------
// Prep (single launch): round all weights fp32->fp16, pack qkv bias.
// ---------------------------------------------------------------------------
#define NW1 (DMODEL * DMODEL / 4)          // 262144 float4 per 1024x1024
#define NW4 (DFF * DMODEL / 4)             // 1048576 float4 per 4096x1024
#define PREP_W (4 * NW1 + 2 * NW4)         // 3,145,728 float4
#define PREP_GRID (PREP_W / 256 + 12)      // + 3072 bias lanes

__global__ void prep_all(
    const float* __restrict__ wq, const float* __restrict__ wk,
    const float* __restrict__ wv, const float* __restrict__ wo,
    const float* __restrict__ w1, const float* __restrict__ w2,
    const float* __restrict__ bq, const float* __restrict__ bk,
    const float* __restrict__ bv,
    __half* __restrict__ wqkv, __half* __restrict__ wo_h,
    __half* __restrict__ w1_h, __half* __restrict__ w2_h,
    float* __restrict__ bqkv)
{
    const size_t i = (size_t)blockIdx.x * 256 + threadIdx.x;
    if (i < PREP_W) {
        const float* src; __half* dst; size_t off;
        if (i < NW1)                { src = wq; dst = wqkv;                      off = i; }
        else if (i < 2 * NW1)       { src = wk; dst = wqkv + DMODEL * DMODEL;    off = i - NW1; }
        else if (i < 3 * NW1)       { src = wv; dst = wqkv + 2 * DMODEL * DMODEL; off = i - 2 * NW1; }
        else if (i < 4 * NW1)       { src = wo; dst = wo_h; off = i - 3 * NW1; }
        else if (i < 4 * NW1 + NW4) { src = w1; dst = w1_h; off = i - 4 * NW1; }
        else                        { src = w2; dst = w2_h; off = i - 4 * NW1 - NW4; }
        float4 v = ((const float4*)src)[off];
        ((uint2*)dst)[off] = make_uint2(f22h2(v.x, v.y), f22h2(v.z, v.w));
    } else {
        const size_t j = i - PREP_W;       // 0..3071
        if (j < DMODEL)           bqkv[j] = bq[j];
        else if (j < 2 * DMODEL)  bqkv[j] = bk[j - DMODEL];
        else if (j < 3 * DMODEL)  bqkv[j] = bv[j - 2 * DMODEL];
    }
}

// ---------------------------------------------------------------------------
// LayerNorm: one block per row, torch semantics; output fp16.
// ---------------------------------------------------------------------------
__global__ void ln_kernel(const float* __restrict__ x, __half* __restrict__ y,
                          const float* __restrict__ alpha, const float* __restrict__ beta)
{
    const size_t r = blockIdx.x;
    const float* xr = x + r * DMODEL;
    __half* yr = y + r * DMODEL;
    const int t = threadIdx.x;

    float v[4];
    float s = 0.f, ss = 0.f;
#pragma unroll
    for (int it = 0; it < 4; it++) {
        float a = xr[t + it * 256];
        v[it] = a;
        s += a;
        ss += a * a;
    }
    __shared__ float red[2][32];
    const int lane = t & 31, wid = t >> 5;
#pragma unroll
    for (int o = 16; o > 0; o >>= 1) {
        s  += __shfl_down_sync(0xffffffffu, s,  o);
        ss += __shfl_down_sync(0xffffffffu, ss, o);
    }
    if (lane == 0) { red[0][wid] = s; red[1][wid] = ss; }
    __syncthreads();
    if (wid == 0) {
        s  = (lane < 8) ? red[0][lane] : 0.f;
        ss = (lane < 8) ? red[1][lane] : 0.f;
#pragma unroll
        for (int o = 4; o > 0; o >>= 1) {
            s  += __shfl_down_sync(0xffffffffu, s,  o);
            ss += __shfl_down_sync(0xffffffffu, ss, o);
        }
        if (lane == 0) { red[0][0] = s; red[1][0] = ss; }
    }
    __syncthreads();
    s = red[0][0]; ss = red[1][0];

    const float mean = s * (1.0f / DMODEL);
    float var = (ss - s * mean) * (1.0f / (DMODEL - 1));
    var = fmaxf(var, 0.f);
    const float inv = alpha[0] / (sqrtf(var) + LN_EPS);
    const float b0 = beta[0];
#pragma unroll
    for (int it = 0; it < 4; it++)
        yr[t + it * 256] = __float2half_rn((v[it] - mean) * inv + b0);
}

// ---------------------------------------------------------------------------
// Dense GEMM, mma.sync fp16 + ldmatrix (R11-proven):
//   C[.,N](ldc) = op(A[.,K](lda) @ B[N,K](ldb)^T)
// EPI: 1 = +bias,relu -> half   2 = +bias,+residual -> float
//      3 = QKV: +bias; q cols scaled 1/8 (exact); v cols -> vT transposed
// ---------------------------------------------------------------------------
#define GP 36                              // pitch in half2 words
#define NSTAGE 3
#define STG_W (2 * 128 * GP)               // words per stage (A+B)
#define GEMM_SMEM (NSTAGE * STG_W * 4)     // 110,592 B

template <int EPI>
__global__ __launch_bounds__(128, 2) void gemm_mma(
    const __half* __restrict__ A, const __half* __restrict__ B,
    const float* __restrict__ bias, const float* __restrict__ res,
    __half* __restrict__ Ch, float* __restrict__ Cf, __half* __restrict__ vT,
    int K, int lda, int ldb, int ldc)
{
    extern __shared__ uint32_t gsm[];

    const int tid = threadIdx.x;
    const int lane = tid & 31, wid = tid >> 5;
    const int bm = blockIdx.y * 128, bn = blockIdx.x * 128;
    const int wm0 = (wid >> 1) * 64, wn0 = (wid & 1) * 64;
    const int g = lane >> 2, t = lane & 3;

    const int arow = lane & 15;
    const int aw   = (lane >> 4) * 4;
    const int brow = (lane & 7) + ((lane >> 4) & 1) * 8;
    const int bw   = ((lane >> 3) & 1) * 4;

    uint32_t abase[NSTAGE];
#pragma unroll
    for (int s = 0; s < NSTAGE; s++)
        abase[s] = smem_u32(gsm + (size_t)s * STG_W);

    const int NC = K >> 6;     // chunks of 64 halves

#define GEMM_ISSUE(c, s) do {                                                  \
        const __half* Ac_ = A + (size_t)bm * lda + (c) * 64;                   \
        const __half* Bc_ = B + (size_t)bn * ldb + (c) * 64;                   \
        const uint32_t ab_ = abase[s], bb_ = abase[s] + 128 * GP * 4;          \
        _Pragma("unroll")                                                      \
        for (int i_ = 0; i_ < 8; i_++) {                                       \
            const int idx_ = tid + i_ * 128;                                   \
            const int row_ = idx_ >> 3, gr_ = idx_ & 7;                        \
            const uint32_t off_ = (uint32_t)(row_ * (GP * 4) + gr_ * 16);      \
            CP_ASYNC16(ab_ + off_, Ac_ + (size_t)row_ * lda + gr_ * 8);        \
            CP_ASYNC16(bb_ + off_, Bc_ + (size_t)row_ * ldb + gr_ * 8);        \
        }                                                                      \
        CP_COMMIT();                                                           \
    } while (0)

    GEMM_ISSUE(0, 0);
    GEMM_ISSUE(1, 1);

    float acc[4][8][4];
#pragma unroll
    for (int mt = 0; mt < 4; mt++)
#pragma unroll
        for (int nt = 0; nt < 8; nt++)
#pragma unroll
            for (int j = 0; j < 4; j++) acc[mt][nt][j] = 0.f;

    for (int c = 0; c < NC; c++) {
        const int st = c % NSTAGE;
        if (c + 2 < NC) {
            GEMM_ISSUE(c + 2, (c + 2) % NSTAGE);
            CP_WAIT(2);
        } else if (c + 1 < NC) {
            CP_WAIT(1);
        } else {
            CP_WAIT(0);
        }
        __syncthreads();

        const uint32_t a_st = abase[st];
        const uint32_t b_st = a_st + 128 * GP * 4;
#pragma unroll
        for (int ks = 0; ks < 4; ks++) {
            uint32_t afr[4][4], bfr[8][2];
#pragma unroll
            for (int mt = 0; mt < 4; mt++) {
                const uint32_t addr = a_st +
                    (uint32_t)(((wm0 + mt * 16 + arow) * GP + ks * 8 + aw) * 4);
                LDSM_X4(afr[mt][0], afr[mt][1], afr[mt][2], afr[mt][3], addr);
            }
#pragma unroll
            for (int j = 0; j < 4; j++) {
                const uint32_t addr = b_st +
                    (uint32_t)(((wn0 + j * 16 + brow) * GP + ks * 8 + bw) * 4);
                LDSM_X4(bfr[2 * j][0], bfr[2 * j][1],
                        bfr[2 * j + 1][0], bfr[2 * j + 1][1], addr);
            }
#pragma unroll
            for (int mt = 0; mt < 4; mt++)
#pragma unroll
                for (int nt = 0; nt < 8; nt++)
                    mma_f16(acc[mt][nt], afr[mt], bfr[nt]);
        }
        __syncthreads();
    }
#undef GEMM_ISSUE

#pragma unroll
    for (int mt = 0; mt < 4; mt++) {
        const int row = bm + wm0 + mt * 16 + g;
#pragma unroll
        for (int nt = 0; nt < 8; nt++) {
            const int col = bn + wn0 + nt * 8 + 2 * t;
            const float b0 = bias[col], b1 = bias[col + 1];
#pragma unroll
            for (int half = 0; half < 2; half++) {
                const int r = row + half * 8;
                float v0 = acc[mt][nt][half * 2 + 0] + b0;
                float v1 = acc[mt][nt][half * 2 + 1] + b1;
                if (EPI == 1) {
                    v0 = fmaxf(v0, 0.f); v1 = fmaxf(v1, 0.f);
                    *(uint32_t*)&Ch[(size_t)r * ldc + col] = f22h2(v0, v1);
                }
                if (EPI == 2) {
                    const float* rr = res + (size_t)r * ldc + col;
                    float* cr = Cf + (size_t)r * ldc + col;
                    cr[0] = v0 + rr[0]; cr[1] = v1 + rr[1];
                }
                if (EPI == 3) {
                    if (col < 2048) {
                        if (col < 1024) { v0 *= 0.125f; v1 *= 0.125f; }  // exact
                        *(uint32_t*)&Ch[(size_t)r * ldc + col] = f22h2(v0, v1);
                    } else {
                        const int cv = col - 2048;        // h*64+d
                        const int s_ = r & (SEQ - 1), bb = r >> 11;
                        __half* vp = vT + (size_t)(bb * 1024 + cv) * SEQ + s_;
                        vp[0]   = __float2half_rn(v0);
                        vp[SEQ] = __float2half_rn(v1);
                    }
                }
            }
        }
    }
}

// ---------------------------------------------------------------------------
// Flash attention, fp16 MMAs + ldmatrix fragment loads.
// BQ=64, 128 threads = 4 warps; q pre-scaled by 1/8; additive float mask;
// V pre-transposed (g_vT). K single-buffered, VT double-buffered via cp.async.
// ---------------------------------------------------------------------------
#define BQ  64
#define BKV 64
#define FP 36                               // pitch in half2 words
#define TILE_W (64 * FP)                    // words per 64-row tile
#define FLASH_SMEM (5 * TILE_W * 4 + BKV * 4)

__global__ __launch_bounds__(128, 3) void flash_attn(
    const __half* __restrict__ qkv, const __half* __restrict__ vT,
    const int* __restrict__ mask, __half* __restrict__ out)
{
    extern __shared__ uint32_t fsm[];
    uint32_t* Qs  = fsm;                    // [64][FP]
    uint32_t* Ks  = Qs  + TILE_W;
    uint32_t* VT0 = Ks  + TILE_W;
    uint32_t* VT1 = VT0 + TILE_W;
    uint32_t* Ps  = VT1 + TILE_W;
    float* mskf = (float*)(Ps + TILE_W);    // [BKV] additive mask

    const int bh = blockIdx.y;
    const int b = bh / NHEAD, h = bh % NHEAD;
    const int qi0 = blockIdx.x * BQ;
    const __half* Qg  = qkv + ((size_t)(b * SEQ + qi0)) * QKV_LD + h * DK;
    const __half* Kg  = qkv + ((size_t)b * SEQ) * QKV_LD + DMODEL + h * DK;
    const __half* Vtg = vT + (size_t)(b * 1024 + h * DK) * SEQ;  // rows d, ld SEQ

    const int tid = threadIdx.x;
    const int lane = tid & 31, wid = tid >> 5;
    const int g = lane >> 2, t = lane & 3;
    const int ar = wid * 16 + g;
    const int c2 = 2 * t;

    const int arow = lane & 15;
    const int aw   = (lane >> 4) * 4;
    const int brow = (lane & 7) + ((lane >> 4) & 1) * 8;
    const int bw   = ((lane >> 3) & 1) * 4;

    const uint32_t qs_a = smem_u32(Qs), ks_a = smem_u32(Ks), ps_a = smem_u32(Ps);
    const uint32_t vt_a[2] = { smem_u32(VT0), smem_u32(VT1) };

#define FL_ISSUE(gptr, ldh, saddr) do {                                        \
        _Pragma("unroll")                                                      \
        for (int i_ = 0; i_ < 4; i_++) {                                       \
            const int idx_ = tid + i_ * 128;                                   \
            const int row_ = idx_ >> 3, gr_ = idx_ & 7;                        \
            CP_ASYNC16((saddr) + (uint32_t)(row_ * (FP * 4) + gr_ * 16),       \
                       (gptr) + (size_t)row_ * (ldh) + gr_ * 8);               \
        }                                                                      \
    } while (0)

    FL_ISSUE(Qg, QKV_LD, qs_a);
    FL_ISSUE(Kg, QKV_LD, ks_a);
    FL_ISSUE(Vtg, SEQ, vt_a[0]);
    CP_COMMIT();

    float m0 = -INFINITY, m1 = -INFINITY, l0 = 0.f, l1 = 0.f;
    float o[8][4];
#pragma unroll
    for (int nt = 0; nt < 8; nt++)
#pragma unroll
        for (int j = 0; j < 4; j++) o[nt][j] = 0.f;

    const int NT = SEQ / BKV;               // 32 tiles
    for (int tile = 0; tile < NT; tile++) {
        const int jt = tile * BKV;
        CP_WAIT(0);
        __syncthreads();
        if (tid < BKV)
            mskf[tid] = mask[(size_t)b * SEQ + jt + tid] ? 0.f : -1e9f;

        // ---- S = Q @ K^T (q pre-scaled) ----
        float s[8][4];
#pragma unroll
        for (int nt = 0; nt < 8; nt++)
#pragma unroll
            for (int j = 0; j < 4; j++) s[nt][j] = 0.f;

#pragma unroll
        for (int ks = 0; ks < 4; ks++) {      // DK=64 -> 4 x k16
            uint32_t a[4], bfr[8][2];
            LDSM_X4(a[0], a[1], a[2], a[3],
                    qs_a + (uint32_t)(((wid * 16 + arow) * FP + ks * 8 + aw) * 4));
#pragma unroll
            for (int j = 0; j < 4; j++)
                LDSM_X4(bfr[2 * j][0], bfr[2 * j][1],
                        bfr[2 * j + 1][0], bfr[2 * j + 1][1],
                        ks_a + (uint32_t)(((j * 16 + brow) * FP + ks * 8 + bw) * 4));
#pragma unroll
            for (int nt = 0; nt < 8; nt++)
                mma_f16(s[nt], a, bfr[nt]);
        }
        __syncthreads();                      // Ks consumed + mskf visible

        if (tile + 1 < NT) {
            FL_ISSUE(Kg + (size_t)(jt + BKV) * QKV_LD, QKV_LD, ks_a);
            FL_ISSUE(Vtg + (jt + BKV), SEQ, vt_a[(tile + 1) & 1]);
            CP_COMMIT();
        }

        // ---- additive mask ----
#pragma unroll
        for (int nt = 0; nt < 8; nt++) {
            const int c0 = nt * 8 + c2;
            const float ma = mskf[c0], mb = mskf[c0 + 1];
            s[nt][0] += ma; s[nt][1] += mb;
            s[nt][2] += ma; s[nt][3] += mb;
        }

        // ---- online softmax ----
        float mx0 = -INFINITY, mx1 = -INFINITY;
#pragma unroll
        for (int nt = 0; nt < 8; nt++) {
            mx0 = fmaxf(mx0, fmaxf(s[nt][0], s[nt][1]));
            mx1 = fmaxf(mx1, fmaxf(s[nt][2], s[nt][3]));
        }
        mx0 = fmaxf(mx0, __shfl_xor_sync(0xffffffffu, mx0, 1));
        mx0 = fmaxf(mx0, __shfl_xor_sync(0xffffffffu, mx0, 2));
        mx1 = fmaxf(mx1, __shfl_xor_sync(0xffffffffu, mx1, 1));
        mx1 = fmaxf(mx1, __shfl_xor_sync(0xffffffffu, mx1, 2));

        const float mn0 = fmaxf(m0, mx0), mn1 = fmaxf(m1, mx1);
        const float sc0 = __expf(m0 - mn0), sc1 = __expf(m1 - mn1);

        float sum0 = 0.f, sum1 = 0.f;
#pragma unroll
        for (int nt = 0; nt < 8; nt++) {
            const float p0 = __expf(s[nt][0] - mn0);
            const float p1 = __expf(s[nt][1] - mn0);
            const float p2 = __expf(s[nt][2] - mn1);
            const float p3 = __expf(s[nt][3] - mn1);
            sum0 += p0 + p1; sum1 += p2 + p3;
            const int pc = nt * 4 + t;        // half2 word col
            Ps[ar * FP + pc]       = f22h2(p0, p1);
            Ps[(ar + 8) * FP + pc] = f22h2(p2, p3);
            o[nt][0] *= sc0; o[nt][1] *= sc0;
            o[nt][2] *= sc1; o[nt][3] *= sc1;
        }
        sum0 += __shfl_xor_sync(0xffffffffu, sum0, 1);
        sum0 += __shfl_xor_sync(0xffffffffu, sum0, 2);
        sum1 += __shfl_xor_sync(0xffffffffu, sum1, 1);
        sum1 += __shfl_xor_sync(0xffffffffu, sum1, 2);
        l0 = l0 * sc0 + sum0;
        l1 = l1 * sc1 + sum1;
        m0 = mn0; m1 = mn1;
        __syncwarp();                         // Ps rows warp-private

        // ---- O += P @ VT^T ----
        const uint32_t vc_a = vt_a[tile & 1];
#pragma unroll
        for (int ks = 0; ks < 4; ks++) {      // j=64 -> 4 x k16
            uint32_t a[4], bfr[8][2];
            LDSM_X4(a[0], a[1], a[2], a[3],
                    ps_a + (uint32_t)(((wid * 16 + arow) * FP + ks * 8 + aw) * 4));
#pragma unroll
            for (int j = 0; j < 4; j++)
                LDSM_X4(bfr[2 * j][0], bfr[2 * j][1],
                        bfr[2 * j + 1][0], bfr[2 * j + 1][1],
                        vc_a + (uint32_t)(((j * 16 + brow) * FP + ks * 8 + bw) * 4));
#pragma unroll
            for (int nt = 0; nt < 8; nt++)
                mma_f16(o[nt], a, bfr[nt]);
        }
    }
#undef FL_ISSUE

    const float inv0 = 1.f / l0, inv1 = 1.f / l1;
    __half* Og = out + ((size_t)(b * SEQ + qi0)) * DMODEL + h * DK;
#pragma unroll
    for (int nt = 0; nt < 8; nt++) {
        const int c0 = nt * 8 + c2;
        *(uint32_t*)&Og[(size_t)ar * DMODEL + c0] =
            f22h2(o[nt][0] * inv0, o[nt][1] * inv0);
        *(uint32_t*)&Og[(size_t)(ar + 8) * DMODEL + c0] =
            f22h2(o[nt][2] * inv1, o[nt][3] * inv1);
    }
}

// ---------------------------------------------------------------------------
// Launch sequence
// ---------------------------------------------------------------------------
extern "C" void kernel_launch(void* const* d_in, const int* in_sizes, int n_in,
                              void* d_out, int out_size)
{
    const float* x    = (const float*)d_in[0];
    const int*   mask = (const int*)  d_in[1];
    const float* wq   = (const float*)d_in[2];
    const float* bq   = (const float*)d_in[3];
    const float* wk   = (const float*)d_in[4];
    const float* bk   = (const float*)d_in[5];
    const float* wv   = (const float*)d_in[6];
    const float* bv   = (const float*)d_in[7];
    const float* wo   = (const float*)d_in[8];
    const float* bo   = (const float*)d_in[9];
    const float* w1   = (const float*)d_in[10];
    const float* b1   = (const float*)d_in[11];
    const float* w2   = (const float*)d_in[12];
    const float* b2   = (const float*)d_in[13];
    const float* a1   = (const float*)d_in[14];
    const float* n1   = (const float*)d_in[15];
    const float* a2   = (const float*)d_in[16];
    const float* n2   = (const float*)d_in[17];
    float* out = (float*)d_out;

    __half *xn, *qkv, *vT, *attn, *ff, *wqkv, *wo_h, *w1_h, *w2_h;
    float *x1, *bqkv;
    cudaGetSymbolAddress((void**)&xn,   g_xn);
    cudaGetSymbolAddress((void**)&qkv,  g_qkv);
    cudaGetSymbolAddress((void**)&vT,   g_vT);
    cudaGetSymbolAddress((void**)&attn, g_attn);
    cudaGetSymbolAddress((void**)&x1,   g_x1);
    cudaGetSymbolAddress((void**)&ff,   g_ff);
    cudaGetSymbolAddress((void**)&wqkv, g_wqkv);
    cudaGetSymbolAddress((void**)&wo_h, g_wo_h);
    cudaGetSymbolAddress((void**)&w1_h, g_w1_h);
    cudaGetSymbolAddress((void**)&w2_h, g_w2_h);
    cudaGetSymbolAddress((void**)&bqkv, g_bqkv);

    cudaFuncSetAttribute(gemm_mma<1>, cudaFuncAttributeMaxDynamicSharedMemorySize, GEMM_SMEM);
    cudaFuncSetAttribute(gemm_mma<2>, cudaFuncAttributeMaxDynamicSharedMemorySize, GEMM_SMEM);
    cudaFuncSetAttribute(gemm_mma<3>, cudaFuncAttributeMaxDynamicSharedMemorySize, GEMM_SMEM);
    cudaFuncSetAttribute(flash_attn,  cudaFuncAttributeMaxDynamicSharedMemorySize, FLASH_SMEM);

    // --- prep: one launch for all weight rounding + bias pack ---
    prep_all<<<PREP_GRID, 256>>>(wq, wk, wv, wo, w1, w2, bq, bk, bv,
                                 wqkv, wo_h, w1_h, w2_h, bqkv);

    // --- residual 1: pre-norm + attention ---
    ln_kernel<<<MTOK, 256>>>(x, xn, a1, n1);

    gemm_mma<3><<<dim3(QKV_LD / 128, MTOK / 128), 128, GEMM_SMEM>>>(
        xn, wqkv, bqkv, nullptr, qkv, nullptr, vT, DMODEL, DMODEL, DMODEL, QKV_LD);

    flash_attn<<<dim3(SEQ / BQ, BATCH * NHEAD), 128, FLASH_SMEM>>>(qkv, vT, mask, attn);

    gemm_mma<2><<<dim3(DMODEL / 128, MTOK / 128), 128, GEMM_SMEM>>>(
        attn, wo_h, bo, x, nullptr, x1, nullptr, DMODEL, DMODEL, DMODEL, DMODEL);

    // --- residual 2: pre-norm + FFN ---
    ln_kernel<<<MTOK, 256>>>(x1, xn, a2, n2);

    gemm_mma<1><<<dim3(DFF / 128, MTOK / 128), 128, GEMM_SMEM>>>(
        xn, w1_h, b1, nullptr, ff, nullptr, nullptr, DMODEL, DMODEL, DMODEL, DFF);

    gemm_mma<2><<<dim3(DMODEL / 128, MTOK / 128), 128, GEMM_SMEM>>>(
        ff, w2_h, b2, x1, nullptr, out, nullptr, DFF, DFF, DFF, DMODEL);
}

// round 13
// speedup vs baseline: 1.0094x; 1.0094x over previous
#include <cuda_runtime.h>
#include <cuda_fp16.h>
#include <math.h>
#include <stdint.h>

// Problem constants
#define BATCH 2
#define SEQ   2048
#define DMODEL 1024
#define NHEAD 16
#define DK    64
#define DFF   4096
#define MTOK  (BATCH * SEQ)           // 4096 tokens
#define QKV_LD 3072
#define LN_EPS 1e-5f

// ---------------- scratch (device globals; no allocation allowed) ----------
__device__ __half g_xn  [(size_t)MTOK * DMODEL];    // fp16 LN out
__device__ __half g_qkv [(size_t)MTOK * QKV_LD];    // fp16 q(pre-scaled),k
__device__ __half g_vT  [(size_t)MTOK * DMODEL];    // fp16 V transposed [b,h,d][s]
__device__ __half g_attn[(size_t)MTOK * DMODEL];    // fp16 attn out
__device__ float  g_x1  [(size_t)MTOK * DMODEL];    // fp32 residual-1
__device__ __half g_ff  [(size_t)MTOK * DFF];       // fp16 relu out
__device__ __half g_wqkv[(size_t)QKV_LD * DMODEL];  // fp16 weights
__device__ __half g_wo_h[(size_t)DMODEL * DMODEL];
__device__ __half g_w1_h[(size_t)DFF * DMODEL];
__device__ __half g_w2_h[(size_t)DMODEL * DFF];
__device__ float  g_bqkv[QKV_LD];

// ============================ helpers ======================================
__device__ __forceinline__ uint32_t smem_u32(const void* p) {
    uint32_t a;
    asm("{ .reg .u64 t; cvta.to.shared.u64 t, %1; cvt.u32.u64 %0, t; }"
        : "=r"(a) : "l"(p));
    return a;
}

__device__ __forceinline__ uint32_t f22h2(float a, float b) {
    __half2 h = __floats2half2_rn(a, b);
    return *reinterpret_cast<uint32_t*>(&h);
}

__device__ __forceinline__ void mma_f16(float* c, const uint32_t* a, const uint32_t* b) {
    asm volatile(
        "mma.sync.aligned.m16n8k16.row.col.f32.f16.f16.f32 "
        "{%0,%1,%2,%3}, {%4,%5,%6,%7}, {%8,%9}, {%0,%1,%2,%3};"
        : "+f"(c[0]), "+f"(c[1]), "+f"(c[2]), "+f"(c[3])
        : "r"(a[0]), "r"(a[1]), "r"(a[2]), "r"(a[3]),
          "r"(b[0]), "r"(b[1]));
}

#define LDSM_X4(r0, r1, r2, r3, addr) \
    asm volatile("ldmatrix.sync.aligned.m8n8.x4.shared.b16 {%0,%1,%2,%3}, [%4];" \
        : "=r"(r0), "=r"(r1), "=r"(r2), "=r"(r3) : "r"(addr))

#define CP_ASYNC16(dst, src) \
    asm volatile("cp.async.cg.shared.global [%0], [%1], 16;" :: \
        "r"(dst), "l"(src) : "memory")
#define CP_COMMIT() asm volatile("cp.async.commit_group;" ::: "memory")
#define CP_WAIT(n)  asm volatile("cp.async.wait_group %0;" :: "n"(n) : "memory")

// ---------------------------------------------------------------------------
// Prep (single launch): round all weights fp32->fp16, pack qkv bias.
// ---------------------------------------------------------------------------
#define NW1 (DMODEL * DMODEL / 4)          // 262144 float4 per 1024x1024
#define NW4 (DFF * DMODEL / 4)             // 1048576 float4 per 4096x1024
#define PREP_W (4 * NW1 + 2 * NW4)         // 3,145,728 float4
#define PREP_GRID (PREP_W / 256 + 12)      // + 3072 bias lanes

__global__ void prep_all(
    const float* __restrict__ wq, const float* __restrict__ wk,
    const float* __restrict__ wv, const float* __restrict__ wo,
    const float* __restrict__ w1, const float* __restrict__ w2,
    const float* __restrict__ bq, const float* __restrict__ bk,
    const float* __restrict__ bv,
    __half* __restrict__ wqkv, __half* __restrict__ wo_h,
    __half* __restrict__ w1_h, __half* __restrict__ w2_h,
    float* __restrict__ bqkv)
{
    const size_t i = (size_t)blockIdx.x * 256 + threadIdx.x;
    if (i < PREP_W) {
        const float* src; __half* dst; size_t off;
        if (i < NW1)                { src = wq; dst = wqkv;                      off = i; }
        else if (i < 2 * NW1)       { src = wk; dst = wqkv + DMODEL * DMODEL;    off = i - NW1; }
        else if (i < 3 * NW1)       { src = wv; dst = wqkv + 2 * DMODEL * DMODEL; off = i - 2 * NW1; }
        else if (i < 4 * NW1)       { src = wo; dst = wo_h; off = i - 3 * NW1; }
        else if (i < 4 * NW1 + NW4) { src = w1; dst = w1_h; off = i - 4 * NW1; }
        else                        { src = w2; dst = w2_h; off = i - 4 * NW1 - NW4; }
        float4 v = ((const float4*)src)[off];
        ((uint2*)dst)[off] = make_uint2(f22h2(v.x, v.y), f22h2(v.z, v.w));
    } else {
        const size_t j = i - PREP_W;       // 0..3071
        if (j < DMODEL)           bqkv[j] = bq[j];
        else if (j < 2 * DMODEL)  bqkv[j] = bk[j - DMODEL];
        else if (j < 3 * DMODEL)  bqkv[j] = bv[j - 2 * DMODEL];
    }
}

// ---------------------------------------------------------------------------
// LayerNorm: one block per row, torch semantics; output fp16.
// ---------------------------------------------------------------------------
__global__ void ln_kernel(const float* __restrict__ x, __half* __restrict__ y,
                          const float* __restrict__ alpha, const float* __restrict__ beta)
{
    const size_t r = blockIdx.x;
    const float* xr = x + r * DMODEL;
    __half* yr = y + r * DMODEL;
    const int t = threadIdx.x;

    float v[4];
    float s = 0.f, ss = 0.f;
#pragma unroll
    for (int it = 0; it < 4; it++) {
        float a = xr[t + it * 256];
        v[it] = a;
        s += a;
        ss += a * a;
    }
    __shared__ float red[2][32];
    const int lane = t & 31, wid = t >> 5;
#pragma unroll
    for (int o = 16; o > 0; o >>= 1) {
        s  += __shfl_down_sync(0xffffffffu, s,  o);
        ss += __shfl_down_sync(0xffffffffu, ss, o);
    }
    if (lane == 0) { red[0][wid] = s; red[1][wid] = ss; }
    __syncthreads();
    if (wid == 0) {
        s  = (lane < 8) ? red[0][lane] : 0.f;
        ss = (lane < 8) ? red[1][lane] : 0.f;
#pragma unroll
        for (int o = 4; o > 0; o >>= 1) {
            s  += __shfl_down_sync(0xffffffffu, s,  o);
            ss += __shfl_down_sync(0xffffffffu, ss, o);
        }
        if (lane == 0) { red[0][0] = s; red[1][0] = ss; }
    }
    __syncthreads();
    s = red[0][0]; ss = red[1][0];

    const float mean = s * (1.0f / DMODEL);
    float var = (ss - s * mean) * (1.0f / (DMODEL - 1));
    var = fmaxf(var, 0.f);
    const float inv = alpha[0] / (sqrtf(var) + LN_EPS);
    const float b0 = beta[0];
#pragma unroll
    for (int it = 0; it < 4; it++)
        yr[t + it * 256] = __float2half_rn((v[it] - mean) * inv + b0);
}

// ---------------------------------------------------------------------------
// Dense GEMM, mma.sync fp16 + ldmatrix (R11/R12-proven):
//   C[.,N](ldc) = op(A[.,K](lda) @ B[N,K](ldb)^T)
// EPI: 1 = +bias,relu -> half   2 = +bias,+residual -> float
//      3 = QKV: +bias; q cols scaled 1/8 (exact); v cols -> vT transposed
// ---------------------------------------------------------------------------
#define GP 36                              // pitch in half2 words
#define NSTAGE 3
#define STG_W (2 * 128 * GP)               // words per stage (A+B)
#define GEMM_SMEM (NSTAGE * STG_W * 4)     // 110,592 B

template <int EPI>
__global__ __launch_bounds__(128, 2) void gemm_mma(
    const __half* __restrict__ A, const __half* __restrict__ B,
    const float* __restrict__ bias, const float* __restrict__ res,
    __half* __restrict__ Ch, float* __restrict__ Cf, __half* __restrict__ vT,
    int K, int lda, int ldb, int ldc)
{
    extern __shared__ uint32_t gsm[];

    const int tid = threadIdx.x;
    const int lane = tid & 31, wid = tid >> 5;
    const int bm = blockIdx.y * 128, bn = blockIdx.x * 128;
    const int wm0 = (wid >> 1) * 64, wn0 = (wid & 1) * 64;
    const int g = lane >> 2, t = lane & 3;

    const int arow = lane & 15;
    const int aw   = (lane >> 4) * 4;
    const int brow = (lane & 7) + ((lane >> 4) & 1) * 8;
    const int bw   = ((lane >> 3) & 1) * 4;

    uint32_t abase[NSTAGE];
#pragma unroll
    for (int s = 0; s < NSTAGE; s++)
        abase[s] = smem_u32(gsm + (size_t)s * STG_W);

    const int NC = K >> 6;     // chunks of 64 halves

#define GEMM_ISSUE(c, s) do {                                                  \
        const __half* Ac_ = A + (size_t)bm * lda + (c) * 64;                   \
        const __half* Bc_ = B + (size_t)bn * ldb + (c) * 64;                   \
        const uint32_t ab_ = abase[s], bb_ = abase[s] + 128 * GP * 4;          \
        _Pragma("unroll")                                                      \
        for (int i_ = 0; i_ < 8; i_++) {                                       \
            const int idx_ = tid + i_ * 128;                                   \
            const int row_ = idx_ >> 3, gr_ = idx_ & 7;                        \
            const uint32_t off_ = (uint32_t)(row_ * (GP * 4) + gr_ * 16);      \
            CP_ASYNC16(ab_ + off_, Ac_ + (size_t)row_ * lda + gr_ * 8);        \
            CP_ASYNC16(bb_ + off_, Bc_ + (size_t)row_ * ldb + gr_ * 8);        \
        }                                                                      \
        CP_COMMIT();                                                           \
    } while (0)

    GEMM_ISSUE(0, 0);
    GEMM_ISSUE(1, 1);

    float acc[4][8][4];
#pragma unroll
    for (int mt = 0; mt < 4; mt++)
#pragma unroll
        for (int nt = 0; nt < 8; nt++)
#pragma unroll
            for (int j = 0; j < 4; j++) acc[mt][nt][j] = 0.f;

    for (int c = 0; c < NC; c++) {
        const int st = c % NSTAGE;
        if (c + 2 < NC) {
            GEMM_ISSUE(c + 2, (c + 2) % NSTAGE);
            CP_WAIT(2);
        } else if (c + 1 < NC) {
            CP_WAIT(1);
        } else {
            CP_WAIT(0);
        }
        __syncthreads();

        const uint32_t a_st = abase[st];
        const uint32_t b_st = a_st + 128 * GP * 4;
#pragma unroll
        for (int ks = 0; ks < 4; ks++) {
            uint32_t afr[4][4], bfr[8][2];
#pragma unroll
            for (int mt = 0; mt < 4; mt++) {
                const uint32_t addr = a_st +
                    (uint32_t)(((wm0 + mt * 16 + arow) * GP + ks * 8 + aw) * 4);
                LDSM_X4(afr[mt][0], afr[mt][1], afr[mt][2], afr[mt][3], addr);
            }
#pragma unroll
            for (int j = 0; j < 4; j++) {
                const uint32_t addr = b_st +
                    (uint32_t)(((wn0 + j * 16 + brow) * GP + ks * 8 + bw) * 4);
                LDSM_X4(bfr[2 * j][0], bfr[2 * j][1],
                        bfr[2 * j + 1][0], bfr[2 * j + 1][1], addr);
            }
#pragma unroll
            for (int mt = 0; mt < 4; mt++)
#pragma unroll
                for (int nt = 0; nt < 8; nt++)
                    mma_f16(acc[mt][nt], afr[mt], bfr[nt]);
        }
        __syncthreads();
    }
#undef GEMM_ISSUE

#pragma unroll
    for (int mt = 0; mt < 4; mt++) {
        const int row = bm + wm0 + mt * 16 + g;
#pragma unroll
        for (int nt = 0; nt < 8; nt++) {
            const int col = bn + wn0 + nt * 8 + 2 * t;
            const float b0 = bias[col], b1 = bias[col + 1];
#pragma unroll
            for (int half = 0; half < 2; half++) {
                const int r = row + half * 8;
                float v0 = acc[mt][nt][half * 2 + 0] + b0;
                float v1 = acc[mt][nt][half * 2 + 1] + b1;
                if (EPI == 1) {
                    v0 = fmaxf(v0, 0.f); v1 = fmaxf(v1, 0.f);
                    *(uint32_t*)&Ch[(size_t)r * ldc + col] = f22h2(v0, v1);
                }
                if (EPI == 2) {
                    const float* rr = res + (size_t)r * ldc + col;
                    float* cr = Cf + (size_t)r * ldc + col;
                    cr[0] = v0 + rr[0]; cr[1] = v1 + rr[1];
                }
                if (EPI == 3) {
                    if (col < 2048) {
                        if (col < 1024) { v0 *= 0.125f; v1 *= 0.125f; }  // exact
                        *(uint32_t*)&Ch[(size_t)r * ldc + col] = f22h2(v0, v1);
                    } else {
                        const int cv = col - 2048;        // h*64+d
                        const int s_ = r & (SEQ - 1), bb = r >> 11;
                        __half* vp = vT + (size_t)(bb * 1024 + cv) * SEQ + s_;
                        vp[0]   = __float2half_rn(v0);
                        vp[SEQ] = __float2half_rn(v1);
                    }
                }
            }
        }
    }
}

// ---------------------------------------------------------------------------
// Flash attention, fp16 MMAs, scalar-LDS fragments (R11-proven), single
// __syncthreads per KV tile: K and V both double-buffered; the whole 2048-
// entry additive mask row preloaded once into SMEM. q pre-scaled by 1/8.
// BQ=64, 128 threads = 4 warps, 3 CTAs/SM.
// ---------------------------------------------------------------------------
#define BQ  64
#define BKV 64
#define FP 36                               // pitch in half2 words
#define TILE_W (64 * FP)                    // words per 64-row tile
#define FLASH_SMEM (6 * TILE_W * 4 + SEQ * 4)   // 63,488 B

__global__ __launch_bounds__(128, 3) void flash_attn(
    const __half* __restrict__ qkv, const __half* __restrict__ vT,
    const int* __restrict__ mask, __half* __restrict__ out)
{
    extern __shared__ uint32_t fsm[];
    uint32_t* Qs  = fsm;                    // [64][FP]
    uint32_t* KT0 = Qs  + TILE_W;
    uint32_t* KT1 = KT0 + TILE_W;
    uint32_t* VT0 = KT1 + TILE_W;
    uint32_t* VT1 = VT0 + TILE_W;
    uint32_t* Ps  = VT1 + TILE_W;
    float* mskf = (float*)(Ps + TILE_W);    // [SEQ] additive mask (whole row)

    const int bh = blockIdx.y;
    const int b = bh / NHEAD, h = bh % NHEAD;
    const int qi0 = blockIdx.x * BQ;
    const __half* Qg  = qkv + ((size_t)(b * SEQ + qi0)) * QKV_LD + h * DK;
    const __half* Kg  = qkv + ((size_t)b * SEQ) * QKV_LD + DMODEL + h * DK;
    const __half* Vtg = vT + (size_t)(b * 1024 + h * DK) * SEQ;

    const int tid = threadIdx.x;
    const int lane = tid & 31, wid = tid >> 5;
    const int g = lane >> 2, t = lane & 3;
    const int ar = wid * 16 + g;
    const int c2 = 2 * t;

    const uint32_t qs_a = smem_u32(Qs);
    const uint32_t kt_a[2] = { smem_u32(KT0), smem_u32(KT1) };
    const uint32_t vt_a[2] = { smem_u32(VT0), smem_u32(VT1) };
    uint32_t* const Kbuf[2] = { KT0, KT1 };
    uint32_t* const Vbuf[2] = { VT0, VT1 };

#define FL_ISSUE(gptr, ldh, saddr) do {                                        \
        _Pragma("unroll")                                                      \
        for (int i_ = 0; i_ < 4; i_++) {                                       \
            const int idx_ = tid + i_ * 128;                                   \
            const int row_ = idx_ >> 3, gr_ = idx_ & 7;                        \
            CP_ASYNC16((saddr) + (uint32_t)(row_ * (FP * 4) + gr_ * 16),       \
                       (gptr) + (size_t)row_ * (ldh) + gr_ * 8);               \
        }                                                                      \
    } while (0)

    // preload Q + K(0) + V(0); mask row via plain LDG/STS (covered by 1st sync)
    FL_ISSUE(Qg, QKV_LD, qs_a);
    FL_ISSUE(Kg, QKV_LD, kt_a[0]);
    FL_ISSUE(Vtg, SEQ, vt_a[0]);
    CP_COMMIT();
#pragma unroll
    for (int i = 0; i < SEQ / 128; i++) {
        const int j = tid + i * 128;
        mskf[j] = mask[(size_t)b * SEQ + j] ? 0.f : -1e9f;
    }

    float m0 = -INFINITY, m1 = -INFINITY, l0 = 0.f, l1 = 0.f;
    float o[8][4];
#pragma unroll
    for (int nt = 0; nt < 8; nt++)
#pragma unroll
        for (int j = 0; j < 4; j++) o[nt][j] = 0.f;

    const int NT = SEQ / BKV;               // 32 tiles
    for (int tile = 0; tile < NT; tile++) {
        const int jt = tile * BKV;
        CP_WAIT(0);
        __syncthreads();    // tile data resident everywhere; prev-tile compute
                            // done -> buffers (tile+1)&1 reusable

        if (tile + 1 < NT) {
            FL_ISSUE(Kg + (size_t)(jt + BKV) * QKV_LD, QKV_LD, kt_a[(tile + 1) & 1]);
            FL_ISSUE(Vtg + (jt + BKV), SEQ, vt_a[(tile + 1) & 1]);
            CP_COMMIT();
        }

        // ---- S = Q @ K^T (q pre-scaled) ----
        const uint32_t* Kc = Kbuf[tile & 1];
        float s[8][4];
#pragma unroll
        for (int nt = 0; nt < 8; nt++)
#pragma unroll
            for (int j = 0; j < 4; j++) s[nt][j] = 0.f;

#pragma unroll
        for (int ks = 0; ks < 4; ks++) {      // DK=64 -> 4 x k16
            const int kc = ks * 8 + t;
            uint32_t a[4];
            a[0] = Qs[ar * FP + kc];
            a[1] = Qs[(ar + 8) * FP + kc];
            a[2] = Qs[ar * FP + kc + 4];
            a[3] = Qs[(ar + 8) * FP + kc + 4];
#pragma unroll
            for (int nt = 0; nt < 8; nt++) {
                const int rn = nt * 8 + g;
                uint32_t bb[2] = { Kc[rn * FP + kc], Kc[rn * FP + kc + 4] };
                mma_f16(s[nt], a, bb);
            }
        }

        // ---- additive mask (SMEM, preloaded) ----
#pragma unroll
        for (int nt = 0; nt < 8; nt++) {
            const int c0 = jt + nt * 8 + c2;
            const float ma = mskf[c0], mb = mskf[c0 + 1];
            s[nt][0] += ma; s[nt][1] += mb;
            s[nt][2] += ma; s[nt][3] += mb;
        }

        // ---- online softmax ----
        float mx0 = -INFINITY, mx1 = -INFINITY;
#pragma unroll
        for (int nt = 0; nt < 8; nt++) {
            mx0 = fmaxf(mx0, fmaxf(s[nt][0], s[nt][1]));
            mx1 = fmaxf(mx1, fmaxf(s[nt][2], s[nt][3]));
        }
        mx0 = fmaxf(mx0, __shfl_xor_sync(0xffffffffu, mx0, 1));
        mx0 = fmaxf(mx0, __shfl_xor_sync(0xffffffffu, mx0, 2));
        mx1 = fmaxf(mx1, __shfl_xor_sync(0xffffffffu, mx1, 1));
        mx1 = fmaxf(mx1, __shfl_xor_sync(0xffffffffu, mx1, 2));

        const float mn0 = fmaxf(m0, mx0), mn1 = fmaxf(m1, mx1);
        const float sc0 = __expf(m0 - mn0), sc1 = __expf(m1 - mn1);

        float sum0 = 0.f, sum1 = 0.f;
#pragma unroll
        for (int nt = 0; nt < 8; nt++) {
            const float p0 = __expf(s[nt][0] - mn0);
            const float p1 = __expf(s[nt][1] - mn0);
            const float p2 = __expf(s[nt][2] - mn1);
            const float p3 = __expf(s[nt][3] - mn1);
            sum0 += p0 + p1; sum1 += p2 + p3;
            const int pc = nt * 4 + t;        // half2 word col
            Ps[ar * FP + pc]       = f22h2(p0, p1);
            Ps[(ar + 8) * FP + pc] = f22h2(p2, p3);
            o[nt][0] *= sc0; o[nt][1] *= sc0;
            o[nt][2] *= sc1; o[nt][3] *= sc1;
        }
        sum0 += __shfl_xor_sync(0xffffffffu, sum0, 1);
        sum0 += __shfl_xor_sync(0xffffffffu, sum0, 2);
        sum1 += __shfl_xor_sync(0xffffffffu, sum1, 1);
        sum1 += __shfl_xor_sync(0xffffffffu, sum1, 2);
        l0 = l0 * sc0 + sum0;
        l1 = l1 * sc1 + sum1;
        m0 = mn0; m1 = mn1;
        __syncwarp();                         // Ps rows warp-private

        // ---- O += P @ VT^T ----
        const uint32_t* Vc = Vbuf[tile & 1];
#pragma unroll
        for (int ks = 0; ks < 4; ks++) {      // j=64 -> 4 x k16
            const int kc = ks * 8 + t;
            uint32_t a[4];
            a[0] = Ps[ar * FP + kc];
            a[1] = Ps[(ar + 8) * FP + kc];
            a[2] = Ps[ar * FP + kc + 4];
            a[3] = Ps[(ar + 8) * FP + kc + 4];
#pragma unroll
            for (int nt = 0; nt < 8; nt++) {
                const int rn = nt * 8 + g;
                uint32_t bb[2] = { Vc[rn * FP + kc], Vc[rn * FP + kc + 4] };
                mma_f16(o[nt], a, bb);
            }
        }
    }
#undef FL_ISSUE

    const float inv0 = 1.f / l0, inv1 = 1.f / l1;
    __half* Og = out + ((size_t)(b * SEQ + qi0)) * DMODEL + h * DK;
#pragma unroll
    for (int nt = 0; nt < 8; nt++) {
        const int c0 = nt * 8 + c2;
        *(uint32_t*)&Og[(size_t)ar * DMODEL + c0] =
            f22h2(o[nt][0] * inv0, o[nt][1] * inv0);
        *(uint32_t*)&Og[(size_t)(ar + 8) * DMODEL + c0] =
            f22h2(o[nt][2] * inv1, o[nt][3] * inv1);
    }
}

// ---------------------------------------------------------------------------
// Launch sequence
// ---------------------------------------------------------------------------
extern "C" void kernel_launch(void* const* d_in, const int* in_sizes, int n_in,
                              void* d_out, int out_size)
{
    const float* x    = (const float*)d_in[0];
    const int*   mask = (const int*)  d_in[1];
    const float* wq   = (const float*)d_in[2];
    const float* bq   = (const float*)d_in[3];
    const float* wk   = (const float*)d_in[4];
    const float* bk   = (const float*)d_in[5];
    const float* wv   = (const float*)d_in[6];
    const float* bv   = (const float*)d_in[7];
    const float* wo   = (const float*)d_in[8];
    const float* bo   = (const float*)d_in[9];
    const float* w1   = (const float*)d_in[10];
    const float* b1   = (const float*)d_in[11];
    const float* w2   = (const float*)d_in[12];
    const float* b2   = (const float*)d_in[13];
    const float* a1   = (const float*)d_in[14];
    const float* n1   = (const float*)d_in[15];
    const float* a2   = (const float*)d_in[16];
    const float* n2   = (const float*)d_in[17];
    float* out = (float*)d_out;

    __half *xn, *qkv, *vT, *attn, *ff, *wqkv, *wo_h, *w1_h, *w2_h;
    float *x1, *bqkv;
    cudaGetSymbolAddress((void**)&xn,   g_xn);
    cudaGetSymbolAddress((void**)&qkv,  g_qkv);
    cudaGetSymbolAddress((void**)&vT,   g_vT);
    cudaGetSymbolAddress((void**)&attn, g_attn);
    cudaGetSymbolAddress((void**)&x1,   g_x1);
    cudaGetSymbolAddress((void**)&ff,   g_ff);
    cudaGetSymbolAddress((void**)&wqkv, g_wqkv);
    cudaGetSymbolAddress((void**)&wo_h, g_wo_h);
    cudaGetSymbolAddress((void**)&w1_h, g_w1_h);
    cudaGetSymbolAddress((void**)&w2_h, g_w2_h);
    cudaGetSymbolAddress((void**)&bqkv, g_bqkv);

    cudaFuncSetAttribute(gemm_mma<1>, cudaFuncAttributeMaxDynamicSharedMemorySize, GEMM_SMEM);
    cudaFuncSetAttribute(gemm_mma<2>, cudaFuncAttributeMaxDynamicSharedMemorySize, GEMM_SMEM);
    cudaFuncSetAttribute(gemm_mma<3>, cudaFuncAttributeMaxDynamicSharedMemorySize, GEMM_SMEM);
    cudaFuncSetAttribute(flash_attn,  cudaFuncAttributeMaxDynamicSharedMemorySize, FLASH_SMEM);

    // --- prep: one launch for all weight rounding + bias pack ---
    prep_all<<<PREP_GRID, 256>>>(wq, wk, wv, wo, w1, w2, bq, bk, bv,
                                 wqkv, wo_h, w1_h, w2_h, bqkv);

    // --- residual 1: pre-norm + attention ---
    ln_kernel<<<MTOK, 256>>>(x, xn, a1, n1);

    gemm_mma<3><<<dim3(QKV_LD / 128, MTOK / 128), 128, GEMM_SMEM>>>(
        xn, wqkv, bqkv, nullptr, qkv, nullptr, vT, DMODEL, DMODEL, DMODEL, QKV_LD);

    flash_attn<<<dim3(SEQ / BQ, BATCH * NHEAD), 128, FLASH_SMEM>>>(qkv, vT, mask, attn);

    gemm_mma<2><<<dim3(DMODEL / 128, MTOK / 128), 128, GEMM_SMEM>>>(
        attn, wo_h, bo, x, nullptr, x1, nullptr, DMODEL, DMODEL, DMODEL, DMODEL);

    // --- residual 2: pre-norm + FFN ---
    ln_kernel<<<MTOK, 256>>>(x1, xn, a2, n2);

    gemm_mma<1><<<dim3(DFF / 128, MTOK / 128), 128, GEMM_SMEM>>>(
        xn, w1_h, b1, nullptr, ff, nullptr, nullptr, DMODEL, DMODEL, DMODEL, DFF);

    gemm_mma<2><<<dim3(DMODEL / 128, MTOK / 128), 128, GEMM_SMEM>>>(
        ff, w2_h, b2, x1, nullptr, out, nullptr, DFF, DFF, DFF, DMODEL);
}

// round 16
// speedup vs baseline: 1.0503x; 1.0406x over previous
#include <cuda_runtime.h>
#include <cuda_fp16.h>
#include <math.h>
#include <stdint.h>

// Problem constants
#define BATCH 2
#define SEQ   2048
#define DMODEL 1024
#define NHEAD 16
#define DK    64
#define DFF   4096
#define MTOK  (BATCH * SEQ)           // 4096 tokens
#define QKV_LD 3072
#define LN_EPS 1e-5f

// ---------------- scratch (device globals; no allocation allowed) ----------
__device__ __half g_xn  [(size_t)MTOK * DMODEL];    // fp16 LN out
__device__ __half g_qkv [(size_t)MTOK * QKV_LD];    // fp16 q(pre-scaled),k
__device__ __half g_vT  [(size_t)MTOK * DMODEL];    // fp16 V transposed [b,h,d][s]
__device__ __half g_attn[(size_t)MTOK * DMODEL];    // fp16 attn out
__device__ float  g_x1  [(size_t)MTOK * DMODEL];    // fp32 residual-1
__device__ __half g_ff  [(size_t)MTOK * DFF];       // fp16 relu out
__device__ __half g_wqkv[(size_t)QKV_LD * DMODEL];  // fp16 weights
__device__ __half g_wo_h[(size_t)DMODEL * DMODEL];
__device__ __half g_w1_h[(size_t)DFF * DMODEL];
__device__ __half g_w2_h[(size_t)DMODEL * DFF];
__device__ float  g_bqkv[QKV_LD];

// ============================ helpers ======================================
__device__ __forceinline__ uint32_t smem_u32(const void* p) {
    uint32_t a;
    asm("{ .reg .u64 t; cvta.to.shared.u64 t, %1; cvt.u32.u64 %0, t; }"
        : "=r"(a) : "l"(p));
    return a;
}

__device__ __forceinline__ uint32_t f22h2(float a, float b) {
    __half2 h = __floats2half2_rn(a, b);
    return *reinterpret_cast<uint32_t*>(&h);
}

__device__ __forceinline__ void mma_f16(float* c, const uint32_t* a, const uint32_t* b) {
    asm volatile(
        "mma.sync.aligned.m16n8k16.row.col.f32.f16.f16.f32 "
        "{%0,%1,%2,%3}, {%4,%5,%6,%7}, {%8,%9}, {%0,%1,%2,%3};"
        : "+f"(c[0]), "+f"(c[1]), "+f"(c[2]), "+f"(c[3])
        : "r"(a[0]), "r"(a[1]), "r"(a[2]), "r"(a[3]),
          "r"(b[0]), "r"(b[1]));
}

#define LDSM_X4(r0, r1, r2, r3, addr) \
    asm volatile("ldmatrix.sync.aligned.m8n8.x4.shared.b16 {%0,%1,%2,%3}, [%4];" \
        : "=r"(r0), "=r"(r1), "=r"(r2), "=r"(r3) : "r"(addr))

#define CP_ASYNC16(dst, src) \
    asm volatile("cp.async.cg.shared.global [%0], [%1], 16;" :: \
        "r"(dst), "l"(src) : "memory")
#define CP_COMMIT() asm volatile("cp.async.commit_group;" ::: "memory")
#define CP_WAIT(n)  asm volatile("cp.async.wait_group %0;" :: "n"(n) : "memory")

// ---------------------------------------------------------------------------
// Prep (single launch): round all weights fp32->fp16, pack qkv bias.
// ---------------------------------------------------------------------------
#define NW1 (DMODEL * DMODEL / 4)          // 262144 float4 per 1024x1024
#define NW4 (DFF * DMODEL / 4)             // 1048576 float4 per 4096x1024
#define PREP_W (4 * NW1 + 2 * NW4)         // 3,145,728 float4
#define PREP_GRID (PREP_W / 256 + 12)      // + 3072 bias lanes

__global__ void prep_all(
    const float* __restrict__ wq, const float* __restrict__ wk,
    const float* __restrict__ wv, const float* __restrict__ wo,
    const float* __restrict__ w1, const float* __restrict__ w2,
    const float* __restrict__ bq, const float* __restrict__ bk,
    const float* __restrict__ bv,
    __half* __restrict__ wqkv, __half* __restrict__ wo_h,
    __half* __restrict__ w1_h, __half* __restrict__ w2_h,
    float* __restrict__ bqkv)
{
    const size_t i = (size_t)blockIdx.x * 256 + threadIdx.x;
    if (i < PREP_W) {
        const float* src; __half* dst; size_t off;
        if (i < NW1)                { src = wq; dst = wqkv;                      off = i; }
        else if (i < 2 * NW1)       { src = wk; dst = wqkv + DMODEL * DMODEL;    off = i - NW1; }
        else if (i < 3 * NW1)       { src = wv; dst = wqkv + 2 * DMODEL * DMODEL; off = i - 2 * NW1; }
        else if (i < 4 * NW1)       { src = wo; dst = wo_h; off = i - 3 * NW1; }
        else if (i < 4 * NW1 + NW4) { src = w1; dst = w1_h; off = i - 4 * NW1; }
        else                        { src = w2; dst = w2_h; off = i - 4 * NW1 - NW4; }
        float4 v = ((const float4*)src)[off];
        ((uint2*)dst)[off] = make_uint2(f22h2(v.x, v.y), f22h2(v.z, v.w));
    } else {
        const size_t j = i - PREP_W;       // 0..3071
        if (j < DMODEL)           bqkv[j] = bq[j];
        else if (j < 2 * DMODEL)  bqkv[j] = bk[j - DMODEL];
        else if (j < 3 * DMODEL)  bqkv[j] = bv[j - 2 * DMODEL];
    }
}

// ---------------------------------------------------------------------------
// LayerNorm: one block per row, torch semantics; output fp16.
// ---------------------------------------------------------------------------
__global__ void ln_kernel(const float* __restrict__ x, __half* __restrict__ y,
                          const float* __restrict__ alpha, const float* __restrict__ beta)
{
    const size_t r = blockIdx.x;
    const float* xr = x + r * DMODEL;
    __half* yr = y + r * DMODEL;
    const int t = threadIdx.x;

    float v[4];
    float s = 0.f, ss = 0.f;
#pragma unroll
    for (int it = 0; it < 4; it++) {
        float a = xr[t + it * 256];
        v[it] = a;
        s += a;
        ss += a * a;
    }
    __shared__ float red[2][32];
    const int lane = t & 31, wid = t >> 5;
#pragma unroll
    for (int o = 16; o > 0; o >>= 1) {
        s  += __shfl_down_sync(0xffffffffu, s,  o);
        ss += __shfl_down_sync(0xffffffffu, ss, o);
    }
    if (lane == 0) { red[0][wid] = s; red[1][wid] = ss; }
    __syncthreads();
    if (wid == 0) {
        s  = (lane < 8) ? red[0][lane] : 0.f;
        ss = (lane < 8) ? red[1][lane] : 0.f;
#pragma unroll
        for (int o = 4; o > 0; o >>= 1) {
            s  += __shfl_down_sync(0xffffffffu, s,  o);
            ss += __shfl_down_sync(0xffffffffu, ss, o);
        }
        if (lane == 0) { red[0][0] = s; red[1][0] = ss; }
    }
    __syncthreads();
    s = red[0][0]; ss = red[1][0];

    const float mean = s * (1.0f / DMODEL);
    float var = (ss - s * mean) * (1.0f / (DMODEL - 1));
    var = fmaxf(var, 0.f);
    const float inv = alpha[0] / (sqrtf(var) + LN_EPS);
    const float b0 = beta[0];
#pragma unroll
    for (int it = 0; it < 4; it++)
        yr[t + it * 256] = __float2half_rn((v[it] - mean) * inv + b0);
}

// ---------------------------------------------------------------------------
// Dense GEMM, mma.sync fp16 + ldmatrix (R11-proven):
//   C[.,N](ldc) = op(A[.,K](lda) @ B[N,K](ldb)^T)
// EPI: 1 = +bias,relu -> half   2 = +bias,+residual -> float
//      3 = QKV: +bias; q cols scaled 1/8 (exact pow2); v cols -> vT transposed
// ---------------------------------------------------------------------------
#define GP 36                              // pitch in half2 words
#define NSTAGE 3
#define STG_W (2 * 128 * GP)               // words per stage (A+B)
#define GEMM_SMEM (NSTAGE * STG_W * 4)     // 110,592 B

template <int EPI>
__global__ __launch_bounds__(128, 2) void gemm_mma(
    const __half* __restrict__ A, const __half* __restrict__ B,
    const float* __restrict__ bias, const float* __restrict__ res,
    __half* __restrict__ Ch, float* __restrict__ Cf, __half* __restrict__ vT,
    int K, int lda, int ldb, int ldc)
{
    extern __shared__ uint32_t gsm[];

    const int tid = threadIdx.x;
    const int lane = tid & 31, wid = tid >> 5;
    const int bm = blockIdx.y * 128, bn = blockIdx.x * 128;
    const int wm0 = (wid >> 1) * 64, wn0 = (wid & 1) * 64;
    const int g = lane >> 2, t = lane & 3;

    const int arow = lane & 15;
    const int aw   = (lane >> 4) * 4;
    const int brow = (lane & 7) + ((lane >> 4) & 1) * 8;
    const int bw   = ((lane >> 3) & 1) * 4;

    uint32_t abase[NSTAGE];
#pragma unroll
    for (int s = 0; s < NSTAGE; s++)
        abase[s] = smem_u32(gsm + (size_t)s * STG_W);

    const int NC = K >> 6;     // chunks of 64 halves

#define GEMM_ISSUE(c, s) do {                                                  \
        const __half* Ac_ = A + (size_t)bm * lda + (c) * 64;                   \
        const __half* Bc_ = B + (size_t)bn * ldb + (c) * 64;                   \
        const uint32_t ab_ = abase[s], bb_ = abase[s] + 128 * GP * 4;          \
        _Pragma("unroll")                                                      \
        for (int i_ = 0; i_ < 8; i_++) {                                       \
            const int idx_ = tid + i_ * 128;                                   \
            const int row_ = idx_ >> 3, gr_ = idx_ & 7;                        \
            const uint32_t off_ = (uint32_t)(row_ * (GP * 4) + gr_ * 16);      \
            CP_ASYNC16(ab_ + off_, Ac_ + (size_t)row_ * lda + gr_ * 8);        \
            CP_ASYNC16(bb_ + off_, Bc_ + (size_t)row_ * ldb + gr_ * 8);        \
        }                                                                      \
        CP_COMMIT();                                                           \
    } while (0)

    GEMM_ISSUE(0, 0);
    GEMM_ISSUE(1, 1);

    float acc[4][8][4];
#pragma unroll
    for (int mt = 0; mt < 4; mt++)
#pragma unroll
        for (int nt = 0; nt < 8; nt++)
#pragma unroll
            for (int j = 0; j < 4; j++) acc[mt][nt][j] = 0.f;

    for (int c = 0; c < NC; c++) {
        const int st = c % NSTAGE;
        if (c + 2 < NC) {
            GEMM_ISSUE(c + 2, (c + 2) % NSTAGE);
            CP_WAIT(2);
        } else if (c + 1 < NC) {
            CP_WAIT(1);
        } else {
            CP_WAIT(0);
        }
        __syncthreads();

        const uint32_t a_st = abase[st];
        const uint32_t b_st = a_st + 128 * GP * 4;
#pragma unroll
        for (int ks = 0; ks < 4; ks++) {
            uint32_t afr[4][4], bfr[8][2];
#pragma unroll
            for (int mt = 0; mt < 4; mt++) {
                const uint32_t addr = a_st +
                    (uint32_t)(((wm0 + mt * 16 + arow) * GP + ks * 8 + aw) * 4);
                LDSM_X4(afr[mt][0], afr[mt][1], afr[mt][2], afr[mt][3], addr);
            }
#pragma unroll
            for (int j = 0; j < 4; j++) {
                const uint32_t addr = b_st +
                    (uint32_t)(((wn0 + j * 16 + brow) * GP + ks * 8 + bw) * 4);
                LDSM_X4(bfr[2 * j][0], bfr[2 * j][1],
                        bfr[2 * j + 1][0], bfr[2 * j + 1][1], addr);
            }
#pragma unroll
            for (int mt = 0; mt < 4; mt++)
#pragma unroll
                for (int nt = 0; nt < 8; nt++)
                    mma_f16(acc[mt][nt], afr[mt], bfr[nt]);
        }
        __syncthreads();
    }
#undef GEMM_ISSUE

#pragma unroll
    for (int mt = 0; mt < 4; mt++) {
        const int row = bm + wm0 + mt * 16 + g;
#pragma unroll
        for (int nt = 0; nt < 8; nt++) {
            const int col = bn + wn0 + nt * 8 + 2 * t;
            const float b0 = bias[col], b1 = bias[col + 1];
#pragma unroll
            for (int half = 0; half < 2; half++) {
                const int r = row + half * 8;
                float v0 = acc[mt][nt][half * 2 + 0] + b0;
                float v1 = acc[mt][nt][half * 2 + 1] + b1;
                if (EPI == 1) {
                    v0 = fmaxf(v0, 0.f); v1 = fmaxf(v1, 0.f);
                    *(uint32_t*)&Ch[(size_t)r * ldc + col] = f22h2(v0, v1);
                }
                if (EPI == 2) {
                    const float* rr = res + (size_t)r * ldc + col;
                    float* cr = Cf + (size_t)r * ldc + col;
                    cr[0] = v0 + rr[0]; cr[1] = v1 + rr[1];
                }
                if (EPI == 3) {
                    if (col < 2048) {
                        if (col < 1024) { v0 *= 0.125f; v1 *= 0.125f; }  // exact
                        *(uint32_t*)&Ch[(size_t)r * ldc + col] = f22h2(v0, v1);
                    } else {
                        const int cv = col - 2048;        // h*64+d
                        const int s_ = r & (SEQ - 1), bb = r >> 11;
                        __half* vp = vT + (size_t)(bb * 1024 + cv) * SEQ + s_;
                        vp[0]   = __float2half_rn(v0);
                        vp[SEQ] = __float2half_rn(v1);
                    }
                }
            }
        }
    }
}

// ---------------------------------------------------------------------------
// Flash attention, fp16 MMAs (R11-proven structure): fused
// scores+mask+softmax+PV. BQ=64, 128 threads = 4 warps; q pre-scaled by 1/8
// (exact) so no S-scaling here; V pre-transposed (g_vT). K single-buffered
// (refill after post-QK sync), VT double-buffered. 2 syncthreads per tile.
// ---------------------------------------------------------------------------
#define BQ  64
#define BKV 64
#define FP 36                               // pitch in half2 words
#define TILE_W (64 * FP)                    // words per 64-row tile
#define FLASH_SMEM (5 * TILE_W * 4 + BKV * 4)

__global__ __launch_bounds__(128, 3) void flash_attn(
    const __half* __restrict__ qkv, const __half* __restrict__ vT,
    const int* __restrict__ mask, __half* __restrict__ out)
{
    extern __shared__ uint32_t fsm[];
    uint32_t* Qs  = fsm;                    // [64][FP]
    uint32_t* Ks  = Qs  + TILE_W;
    uint32_t* VT0 = Ks  + TILE_W;
    uint32_t* VT1 = VT0 + TILE_W;
    uint32_t* Ps  = VT1 + TILE_W;
    int* msk = (int*)(Ps + TILE_W);         // [BKV]

    const int bh = blockIdx.y;
    const int b = bh / NHEAD, h = bh % NHEAD;
    const int qi0 = blockIdx.x * BQ;
    const __half* Qg  = qkv + ((size_t)(b * SEQ + qi0)) * QKV_LD + h * DK;
    const __half* Kg  = qkv + ((size_t)b * SEQ) * QKV_LD + DMODEL + h * DK;
    const __half* Vtg = vT + (size_t)(b * 1024 + h * DK) * SEQ;  // rows d, ld SEQ

    const int tid = threadIdx.x;
    const int lane = tid & 31, wid = tid >> 5;
    const int g = lane >> 2, t = lane & 3;
    const int ar = wid * 16 + g;
    const int c2 = 2 * t;

    const uint32_t qs_a = smem_u32(Qs), ks_a = smem_u32(Ks);
    const uint32_t vt_a[2] = { smem_u32(VT0), smem_u32(VT1) };

#define FL_ISSUE(gptr, ldh, saddr) do {                                        \
        _Pragma("unroll")                                                      \
        for (int i_ = 0; i_ < 4; i_++) {                                       \
            const int idx_ = tid + i_ * 128;                                   \
            const int row_ = idx_ >> 3, gr_ = idx_ & 7;                        \
            CP_ASYNC16((saddr) + (uint32_t)(row_ * (FP * 4) + gr_ * 16),       \
                       (gptr) + (size_t)row_ * (ldh) + gr_ * 8);               \
        }                                                                      \
    } while (0)

    FL_ISSUE(Qg, QKV_LD, qs_a);
    FL_ISSUE(Kg, QKV_LD, ks_a);
    FL_ISSUE(Vtg, SEQ, vt_a[0]);
    CP_COMMIT();

    float m0 = -INFINITY, m1 = -INFINITY, l0 = 0.f, l1 = 0.f;
    float o[8][4];
#pragma unroll
    for (int nt = 0; nt < 8; nt++)
#pragma unroll
        for (int j = 0; j < 4; j++) o[nt][j] = 0.f;

    const int NT = SEQ / BKV;               // 32 tiles
    for (int tile = 0; tile < NT; tile++) {
        const int jt = tile * BKV;
        CP_WAIT(0);
        __syncthreads();
        if (tid < BKV) msk[tid] = mask[(size_t)b * SEQ + jt + tid];

        // ---- S = Q @ K^T (q pre-scaled) ----
        float s[8][4];
#pragma unroll
        for (int nt = 0; nt < 8; nt++)
#pragma unroll
            for (int j = 0; j < 4; j++) s[nt][j] = 0.f;

#pragma unroll
        for (int ks = 0; ks < 4; ks++) {      // DK=64 -> 4 x k16
            const int kc = ks * 8 + t;
            uint32_t a[4];
            a[0] = Qs[ar * FP + kc];
            a[1] = Qs[(ar + 8) * FP + kc];
            a[2] = Qs[ar * FP + kc + 4];
            a[3] = Qs[(ar + 8) * FP + kc + 4];
#pragma unroll
            for (int nt = 0; nt < 8; nt++) {
                const int rn = nt * 8 + g;
                uint32_t bb[2] = { Ks[rn * FP + kc], Ks[rn * FP + kc + 4] };
                mma_f16(s[nt], a, bb);
            }
        }
        __syncthreads();                      // Ks consumed + msk visible

        if (tile + 1 < NT) {
            FL_ISSUE(Kg + (size_t)(jt + BKV) * QKV_LD, QKV_LD, ks_a);
            FL_ISSUE(Vtg + (jt + BKV), SEQ, vt_a[(tile + 1) & 1]);
            CP_COMMIT();
        }

        // ---- mask (S already scaled via q) ----
#pragma unroll
        for (int nt = 0; nt < 8; nt++) {
            const int c0 = nt * 8 + c2;
            if (msk[c0] == 0)     { s[nt][0] = -1e9f; s[nt][2] = -1e9f; }
            if (msk[c0 + 1] == 0) { s[nt][1] = -1e9f; s[nt][3] = -1e9f; }
        }

        // ---- online softmax ----
        float mx0 = -INFINITY, mx1 = -INFINITY;
#pragma unroll
        for (int nt = 0; nt < 8; nt++) {
            mx0 = fmaxf(mx0, fmaxf(s[nt][0], s[nt][1]));
            mx1 = fmaxf(mx1, fmaxf(s[nt][2], s[nt][3]));
        }
        mx0 = fmaxf(mx0, __shfl_xor_sync(0xffffffffu, mx0, 1));
        mx0 = fmaxf(mx0, __shfl_xor_sync(0xffffffffu, mx0, 2));
        mx1 = fmaxf(mx1, __shfl_xor_sync(0xffffffffu, mx1, 1));
        mx1 = fmaxf(mx1, __shfl_xor_sync(0xffffffffu, mx1, 2));

        const float mn0 = fmaxf(m0, mx0), mn1 = fmaxf(m1, mx1);
        const float sc0 = __expf(m0 - mn0), sc1 = __expf(m1 - mn1);

        float sum0 = 0.f, sum1 = 0.f;
#pragma unroll
        for (int nt = 0; nt < 8; nt++) {
            const float p0 = __expf(s[nt][0] - mn0);
            const float p1 = __expf(s[nt][1] - mn0);
            const float p2 = __expf(s[nt][2] - mn1);
            const float p3 = __expf(s[nt][3] - mn1);
            sum0 += p0 + p1; sum1 += p2 + p3;
            const int pc = nt * 4 + t;        // half2 word col
            Ps[ar * FP + pc]       = f22h2(p0, p1);
            Ps[(ar + 8) * FP + pc] = f22h2(p2, p3);
            o[nt][0] *= sc0; o[nt][1] *= sc0;
            o[nt][2] *= sc1; o[nt][3] *= sc1;
        }
        sum0 += __shfl_xor_sync(0xffffffffu, sum0, 1);
        sum0 += __shfl_xor_sync(0xffffffffu, sum0, 2);
        sum1 += __shfl_xor_sync(0xffffffffu, sum1, 1);
        sum1 += __shfl_xor_sync(0xffffffffu, sum1, 2);
        l0 = l0 * sc0 + sum0;
        l1 = l1 * sc1 + sum1;
        m0 = mn0; m1 = mn1;
        __syncwarp();                         // Ps rows warp-private

        // ---- O += P @ VT^T ----
        const uint32_t* Vc = (tile & 1) ? VT1 : VT0;
#pragma unroll
        for (int ks = 0; ks < 4; ks++) {      // j=64 -> 4 x k16
            const int kc = ks * 8 + t;
            uint32_t a[4];
            a[0] = Ps[ar * FP + kc];
            a[1] = Ps[(ar + 8) * FP + kc];
            a[2] = Ps[ar * FP + kc + 4];
            a[3] = Ps[(ar + 8) * FP + kc + 4];
#pragma unroll
            for (int nt = 0; nt < 8; nt++) {
                const int rn = nt * 8 + g;
                uint32_t bb[2] = { Vc[rn * FP + kc], Vc[rn * FP + kc + 4] };
                mma_f16(o[nt], a, bb);
            }
        }
    }
#undef FL_ISSUE

    const float inv0 = 1.f / l0, inv1 = 1.f / l1;
    __half* Og = out + ((size_t)(b * SEQ + qi0)) * DMODEL + h * DK;
#pragma unroll
    for (int nt = 0; nt < 8; nt++) {
        const int c0 = nt * 8 + c2;
        *(uint32_t*)&Og[(size_t)ar * DMODEL + c0] =
            f22h2(o[nt][0] * inv0, o[nt][1] * inv0);
        *(uint32_t*)&Og[(size_t)(ar + 8) * DMODEL + c0] =
            f22h2(o[nt][2] * inv1, o[nt][3] * inv1);
    }
}

// ---------------------------------------------------------------------------
// Launch sequence
// ---------------------------------------------------------------------------
extern "C" void kernel_launch(void* const* d_in, const int* in_sizes, int n_in,
                              void* d_out, int out_size)
{
    const float* x    = (const float*)d_in[0];
    const int*   mask = (const int*)  d_in[1];
    const float* wq   = (const float*)d_in[2];
    const float* bq   = (const float*)d_in[3];
    const float* wk   = (const float*)d_in[4];
    const float* bk   = (const float*)d_in[5];
    const float* wv   = (const float*)d_in[6];
    const float* bv   = (const float*)d_in[7];
    const float* wo   = (const float*)d_in[8];
    const float* bo   = (const float*)d_in[9];
    const float* w1   = (const float*)d_in[10];
    const float* b1   = (const float*)d_in[11];
    const float* w2   = (const float*)d_in[12];
    const float* b2   = (const float*)d_in[13];
    const float* a1   = (const float*)d_in[14];
    const float* n1   = (const float*)d_in[15];
    const float* a2   = (const float*)d_in[16];
    const float* n2   = (const float*)d_in[17];
    float* out = (float*)d_out;

    __half *xn, *qkv, *vT, *attn, *ff, *wqkv, *wo_h, *w1_h, *w2_h;
    float *x1, *bqkv;
    cudaGetSymbolAddress((void**)&xn,   g_xn);
    cudaGetSymbolAddress((void**)&qkv,  g_qkv);
    cudaGetSymbolAddress((void**)&vT,   g_vT);
    cudaGetSymbolAddress((void**)&attn, g_attn);
    cudaGetSymbolAddress((void**)&x1,   g_x1);
    cudaGetSymbolAddress((void**)&ff,   g_ff);
    cudaGetSymbolAddress((void**)&wqkv, g_wqkv);
    cudaGetSymbolAddress((void**)&wo_h, g_wo_h);
    cudaGetSymbolAddress((void**)&w1_h, g_w1_h);
    cudaGetSymbolAddress((void**)&w2_h, g_w2_h);
    cudaGetSymbolAddress((void**)&bqkv, g_bqkv);

    cudaFuncSetAttribute(gemm_mma<1>, cudaFuncAttributeMaxDynamicSharedMemorySize, GEMM_SMEM);
    cudaFuncSetAttribute(gemm_mma<2>, cudaFuncAttributeMaxDynamicSharedMemorySize, GEMM_SMEM);
    cudaFuncSetAttribute(gemm_mma<3>, cudaFuncAttributeMaxDynamicSharedMemorySize, GEMM_SMEM);
    cudaFuncSetAttribute(flash_attn,  cudaFuncAttributeMaxDynamicSharedMemorySize, FLASH_SMEM);

    // --- prep: one launch for all weight rounding + bias pack ---
    prep_all<<<PREP_GRID, 256>>>(wq, wk, wv, wo, w1, w2, bq, bk, bv,
                                 wqkv, wo_h, w1_h, w2_h, bqkv);

    // --- residual 1: pre-norm + attention ---
    ln_kernel<<<MTOK, 256>>>(x, xn, a1, n1);

    gemm_mma<3><<<dim3(QKV_LD / 128, MTOK / 128), 128, GEMM_SMEM>>>(
        xn, wqkv, bqkv, nullptr, qkv, nullptr, vT, DMODEL, DMODEL, DMODEL, QKV_LD);

    flash_attn<<<dim3(SEQ / BQ, BATCH * NHEAD), 128, FLASH_SMEM>>>(qkv, vT, mask, attn);

    gemm_mma<2><<<dim3(DMODEL / 128, MTOK / 128), 128, GEMM_SMEM>>>(
        attn, wo_h, bo, x, nullptr, x1, nullptr, DMODEL, DMODEL, DMODEL, DMODEL);

    // --- residual 2: pre-norm + FFN ---
    ln_kernel<<<MTOK, 256>>>(x1, xn, a2, n2);

    gemm_mma<1><<<dim3(DFF / 128, MTOK / 128), 128, GEMM_SMEM>>>(
        xn, w1_h, b1, nullptr, ff, nullptr, nullptr, DMODEL, DMODEL, DMODEL, DFF);

    gemm_mma<2><<<dim3(DMODEL / 128, MTOK / 128), 128, GEMM_SMEM>>>(
        ff, w2_h, b2, x1, nullptr, out, nullptr, DFF, DFF, DFF, DMODEL);
}

// round 17
// speedup vs baseline: 1.0565x; 1.0059x over previous
#include <cuda_runtime.h>
#include <cuda_fp16.h>
#include <math.h>
#include <stdint.h>

// Problem constants
#define BATCH 2
#define SEQ   2048
#define DMODEL 1024
#define NHEAD 16
#define DK    64
#define DFF   4096
#define MTOK  (BATCH * SEQ)           // 4096 tokens
#define QKV_LD 3072
#define LN_EPS 1e-5f
// q prescale: (1/sqrt(64)) * log2(e) -> softmax runs in exp2 domain
#define QSCALE 0.1803368801111204f

// ---------------- scratch (device globals; no allocation allowed) ----------
__device__ __half g_xn  [(size_t)MTOK * DMODEL];    // fp16 LN out
__device__ __half g_qkv [(size_t)MTOK * QKV_LD];    // fp16 q(pre-scaled),k
__device__ __half g_vT  [(size_t)MTOK * DMODEL];    // fp16 V transposed [b,h,d][s]
__device__ __half g_attn[(size_t)MTOK * DMODEL];    // fp16 attn out
__device__ float  g_x1  [(size_t)MTOK * DMODEL];    // fp32 residual-1
__device__ __half g_ff  [(size_t)MTOK * DFF];       // fp16 relu out
__device__ __half g_wqkv[(size_t)QKV_LD * DMODEL];  // fp16 weights
__device__ __half g_wo_h[(size_t)DMODEL * DMODEL];
__device__ __half g_w1_h[(size_t)DFF * DMODEL];
__device__ __half g_w2_h[(size_t)DMODEL * DFF];
__device__ float  g_bqkv[QKV_LD];

// ============================ helpers ======================================
__device__ __forceinline__ uint32_t smem_u32(const void* p) {
    uint32_t a;
    asm("{ .reg .u64 t; cvta.to.shared.u64 t, %1; cvt.u32.u64 %0, t; }"
        : "=r"(a) : "l"(p));
    return a;
}

__device__ __forceinline__ uint32_t f22h2(float a, float b) {
    __half2 h = __floats2half2_rn(a, b);
    return *reinterpret_cast<uint32_t*>(&h);
}

__device__ __forceinline__ float ex2(float x) {
    float r;
    asm("ex2.approx.f32 %0, %1;" : "=f"(r) : "f"(x));
    return r;
}

__device__ __forceinline__ void mma_f16(float* c, const uint32_t* a, const uint32_t* b) {
    asm volatile(
        "mma.sync.aligned.m16n8k16.row.col.f32.f16.f16.f32 "
        "{%0,%1,%2,%3}, {%4,%5,%6,%7}, {%8,%9}, {%0,%1,%2,%3};"
        : "+f"(c[0]), "+f"(c[1]), "+f"(c[2]), "+f"(c[3])
        : "r"(a[0]), "r"(a[1]), "r"(a[2]), "r"(a[3]),
          "r"(b[0]), "r"(b[1]));
}

#define LDSM_X4(r0, r1, r2, r3, addr) \
    asm volatile("ldmatrix.sync.aligned.m8n8.x4.shared.b16 {%0,%1,%2,%3}, [%4];" \
        : "=r"(r0), "=r"(r1), "=r"(r2), "=r"(r3) : "r"(addr))

#define CP_ASYNC16(dst, src) \
    asm volatile("cp.async.cg.shared.global [%0], [%1], 16;" :: \
        "r"(dst), "l"(src) : "memory")
#define CP_COMMIT() asm volatile("cp.async.commit_group;" ::: "memory")
#define CP_WAIT(n)  asm volatile("cp.async.wait_group %0;" :: "n"(n) : "memory")

// ---------------------------------------------------------------------------
// Prep (single launch): round all weights fp32->fp16, pack qkv bias.
// ---------------------------------------------------------------------------
#define NW1 (DMODEL * DMODEL / 4)          // 262144 float4 per 1024x1024
#define NW4 (DFF * DMODEL / 4)             // 1048576 float4 per 4096x1024
#define PREP_W (4 * NW1 + 2 * NW4)         // 3,145,728 float4
#define PREP_GRID (PREP_W / 256 + 12)      // + 3072 bias lanes

__global__ void prep_all(
    const float* __restrict__ wq, const float* __restrict__ wk,
    const float* __restrict__ wv, const float* __restrict__ wo,
    const float* __restrict__ w1, const float* __restrict__ w2,
    const float* __restrict__ bq, const float* __restrict__ bk,
    const float* __restrict__ bv,
    __half* __restrict__ wqkv, __half* __restrict__ wo_h,
    __half* __restrict__ w1_h, __half* __restrict__ w2_h,
    float* __restrict__ bqkv)
{
    const size_t i = (size_t)blockIdx.x * 256 + threadIdx.x;
    if (i < PREP_W) {
        const float* src; __half* dst; size_t off;
        if (i < NW1)                { src = wq; dst = wqkv;                      off = i; }
        else if (i < 2 * NW1)       { src = wk; dst = wqkv + DMODEL * DMODEL;    off = i - NW1; }
        else if (i < 3 * NW1)       { src = wv; dst = wqkv + 2 * DMODEL * DMODEL; off = i - 2 * NW1; }
        else if (i < 4 * NW1)       { src = wo; dst = wo_h; off = i - 3 * NW1; }
        else if (i < 4 * NW1 + NW4) { src = w1; dst = w1_h; off = i - 4 * NW1; }
        else                        { src = w2; dst = w2_h; off = i - 4 * NW1 - NW4; }
        float4 v = ((const float4*)src)[off];
        ((uint2*)dst)[off] = make_uint2(f22h2(v.x, v.y), f22h2(v.z, v.w));
    } else {
        const size_t j = i - PREP_W;       // 0..3071
        if (j < DMODEL)           bqkv[j] = bq[j];
        else if (j < 2 * DMODEL)  bqkv[j] = bk[j - DMODEL];
        else if (j < 3 * DMODEL)  bqkv[j] = bv[j - 2 * DMODEL];
    }
}

// ---------------------------------------------------------------------------
// LayerNorm: one block per row, torch semantics; output fp16.
// ---------------------------------------------------------------------------
__global__ void ln_kernel(const float* __restrict__ x, __half* __restrict__ y,
                          const float* __restrict__ alpha, const float* __restrict__ beta)
{
    const size_t r = blockIdx.x;
    const float* xr = x + r * DMODEL;
    __half* yr = y + r * DMODEL;
    const int t = threadIdx.x;

    float v[4];
    float s = 0.f, ss = 0.f;
#pragma unroll
    for (int it = 0; it < 4; it++) {
        float a = xr[t + it * 256];
        v[it] = a;
        s += a;
        ss += a * a;
    }
    __shared__ float red[2][32];
    const int lane = t & 31, wid = t >> 5;
#pragma unroll
    for (int o = 16; o > 0; o >>= 1) {
        s  += __shfl_down_sync(0xffffffffu, s,  o);
        ss += __shfl_down_sync(0xffffffffu, ss, o);
    }
    if (lane == 0) { red[0][wid] = s; red[1][wid] = ss; }
    __syncthreads();
    if (wid == 0) {
        s  = (lane < 8) ? red[0][lane] : 0.f;
        ss = (lane < 8) ? red[1][lane] : 0.f;
#pragma unroll
        for (int o = 4; o > 0; o >>= 1) {
            s  += __shfl_down_sync(0xffffffffu, s,  o);
            ss += __shfl_down_sync(0xffffffffu, ss, o);
        }
        if (lane == 0) { red[0][0] = s; red[1][0] = ss; }
    }
    __syncthreads();
    s = red[0][0]; ss = red[1][0];

    const float mean = s * (1.0f / DMODEL);
    float var = (ss - s * mean) * (1.0f / (DMODEL - 1));
    var = fmaxf(var, 0.f);
    const float inv = alpha[0] / (sqrtf(var) + LN_EPS);
    const float b0 = beta[0];
#pragma unroll
    for (int it = 0; it < 4; it++)
        yr[t + it * 256] = __float2half_rn((v[it] - mean) * inv + b0);
}

// ---------------------------------------------------------------------------
// Dense GEMM, mma.sync fp16 + ldmatrix (R11-proven):
//   C[.,N](ldc) = op(A[.,K](lda) @ B[N,K](ldb)^T)
// EPI: 1 = +bias,relu -> half   2 = +bias,+residual -> float
//      3 = QKV: +bias; q cols scaled by QSCALE; v cols -> vT transposed
// ---------------------------------------------------------------------------
#define GP 36                              // pitch in half2 words
#define NSTAGE 3
#define STG_W (2 * 128 * GP)               // words per stage (A+B)
#define GEMM_SMEM (NSTAGE * STG_W * 4)     // 110,592 B

template <int EPI>
__global__ __launch_bounds__(128, 2) void gemm_mma(
    const __half* __restrict__ A, const __half* __restrict__ B,
    const float* __restrict__ bias, const float* __restrict__ res,
    __half* __restrict__ Ch, float* __restrict__ Cf, __half* __restrict__ vT,
    int K, int lda, int ldb, int ldc)
{
    extern __shared__ uint32_t gsm[];

    const int tid = threadIdx.x;
    const int lane = tid & 31, wid = tid >> 5;
    const int bm = blockIdx.y * 128, bn = blockIdx.x * 128;
    const int wm0 = (wid >> 1) * 64, wn0 = (wid & 1) * 64;
    const int g = lane >> 2, t = lane & 3;

    const int arow = lane & 15;
    const int aw   = (lane >> 4) * 4;
    const int brow = (lane & 7) + ((lane >> 4) & 1) * 8;
    const int bw   = ((lane >> 3) & 1) * 4;

    uint32_t abase[NSTAGE];
#pragma unroll
    for (int s = 0; s < NSTAGE; s++)
        abase[s] = smem_u32(gsm + (size_t)s * STG_W);

    const int NC = K >> 6;     // chunks of 64 halves

#define GEMM_ISSUE(c, s) do {                                                  \
        const __half* Ac_ = A + (size_t)bm * lda + (c) * 64;                   \
        const __half* Bc_ = B + (size_t)bn * ldb + (c) * 64;                   \
        const uint32_t ab_ = abase[s], bb_ = abase[s] + 128 * GP * 4;          \
        _Pragma("unroll")                                                      \
        for (int i_ = 0; i_ < 8; i_++) {                                       \
            const int idx_ = tid + i_ * 128;                                   \
            const int row_ = idx_ >> 3, gr_ = idx_ & 7;                        \
            const uint32_t off_ = (uint32_t)(row_ * (GP * 4) + gr_ * 16);      \
            CP_ASYNC16(ab_ + off_, Ac_ + (size_t)row_ * lda + gr_ * 8);        \
            CP_ASYNC16(bb_ + off_, Bc_ + (size_t)row_ * ldb + gr_ * 8);        \
        }                                                                      \
        CP_COMMIT();                                                           \
    } while (0)

    GEMM_ISSUE(0, 0);
    GEMM_ISSUE(1, 1);

    float acc[4][8][4];
#pragma unroll
    for (int mt = 0; mt < 4; mt++)
#pragma unroll
        for (int nt = 0; nt < 8; nt++)
#pragma unroll
            for (int j = 0; j < 4; j++) acc[mt][nt][j] = 0.f;

    for (int c = 0; c < NC; c++) {
        const int st = c % NSTAGE;
        if (c + 2 < NC) {
            GEMM_ISSUE(c + 2, (c + 2) % NSTAGE);
            CP_WAIT(2);
        } else if (c + 1 < NC) {
            CP_WAIT(1);
        } else {
            CP_WAIT(0);
        }
        __syncthreads();

        const uint32_t a_st = abase[st];
        const uint32_t b_st = a_st + 128 * GP * 4;
#pragma unroll
        for (int ks = 0; ks < 4; ks++) {
            uint32_t afr[4][4], bfr[8][2];
#pragma unroll
            for (int mt = 0; mt < 4; mt++) {
                const uint32_t addr = a_st +
                    (uint32_t)(((wm0 + mt * 16 + arow) * GP + ks * 8 + aw) * 4);
                LDSM_X4(afr[mt][0], afr[mt][1], afr[mt][2], afr[mt][3], addr);
            }
#pragma unroll
            for (int j = 0; j < 4; j++) {
                const uint32_t addr = b_st +
                    (uint32_t)(((wn0 + j * 16 + brow) * GP + ks * 8 + bw) * 4);
                LDSM_X4(bfr[2 * j][0], bfr[2 * j][1],
                        bfr[2 * j + 1][0], bfr[2 * j + 1][1], addr);
            }
#pragma unroll
            for (int mt = 0; mt < 4; mt++)
#pragma unroll
                for (int nt = 0; nt < 8; nt++)
                    mma_f16(acc[mt][nt], afr[mt], bfr[nt]);
        }
        __syncthreads();
    }
#undef GEMM_ISSUE

#pragma unroll
    for (int mt = 0; mt < 4; mt++) {
        const int row = bm + wm0 + mt * 16 + g;
#pragma unroll
        for (int nt = 0; nt < 8; nt++) {
            const int col = bn + wn0 + nt * 8 + 2 * t;
            const float b0 = bias[col], b1 = bias[col + 1];
#pragma unroll
            for (int half = 0; half < 2; half++) {
                const int r = row + half * 8;
                float v0 = acc[mt][nt][half * 2 + 0] + b0;
                float v1 = acc[mt][nt][half * 2 + 1] + b1;
                if (EPI == 1) {
                    v0 = fmaxf(v0, 0.f); v1 = fmaxf(v1, 0.f);
                    *(uint32_t*)&Ch[(size_t)r * ldc + col] = f22h2(v0, v1);
                }
                if (EPI == 2) {
                    const float* rr = res + (size_t)r * ldc + col;
                    float* cr = Cf + (size_t)r * ldc + col;
                    cr[0] = v0 + rr[0]; cr[1] = v1 + rr[1];
                }
                if (EPI == 3) {
                    if (col < 2048) {
                        if (col < 1024) { v0 *= QSCALE; v1 *= QSCALE; }
                        *(uint32_t*)&Ch[(size_t)r * ldc + col] = f22h2(v0, v1);
                    } else {
                        const int cv = col - 2048;        // h*64+d
                        const int s_ = r & (SEQ - 1), bb = r >> 11;
                        __half* vp = vT + (size_t)(bb * 1024 + cv) * SEQ + s_;
                        vp[0]   = __float2half_rn(v0);
                        vp[SEQ] = __float2half_rn(v1);
                    }
                }
            }
        }
    }
}

// ---------------------------------------------------------------------------
// Flash attention, fp16 MMAs (R11-proven skeleton), two local edits:
//  - Q fragments hoisted into registers (loaded once at tile 0; Q is SMEM-
//    resident and invariant across all 32 KV tiles)
//  - softmax in exp2 domain (q carries 0.125*log2e; raw ex2.approx)
// BQ=64, 128 threads = 4 warps; V pre-transposed (g_vT); K single-buffered,
// VT double-buffered. 2 syncthreads per tile.
// ---------------------------------------------------------------------------
#define BQ  64
#define BKV 64
#define FP 36                               // pitch in half2 words
#define TILE_W (64 * FP)                    // words per 64-row tile
#define FLASH_SMEM (5 * TILE_W * 4 + BKV * 4)

__global__ __launch_bounds__(128, 3) void flash_attn(
    const __half* __restrict__ qkv, const __half* __restrict__ vT,
    const int* __restrict__ mask, __half* __restrict__ out)
{
    extern __shared__ uint32_t fsm[];
    uint32_t* Qs  = fsm;                    // [64][FP]
    uint32_t* Ks  = Qs  + TILE_W;
    uint32_t* VT0 = Ks  + TILE_W;
    uint32_t* VT1 = VT0 + TILE_W;
    uint32_t* Ps  = VT1 + TILE_W;
    int* msk = (int*)(Ps + TILE_W);         // [BKV]

    const int bh = blockIdx.y;
    const int b = bh / NHEAD, h = bh % NHEAD;
    const int qi0 = blockIdx.x * BQ;
    const __half* Qg  = qkv + ((size_t)(b * SEQ + qi0)) * QKV_LD + h * DK;
    const __half* Kg  = qkv + ((size_t)b * SEQ) * QKV_LD + DMODEL + h * DK;
    const __half* Vtg = vT + (size_t)(b * 1024 + h * DK) * SEQ;  // rows d, ld SEQ

    const int tid = threadIdx.x;
    const int lane = tid & 31, wid = tid >> 5;
    const int g = lane >> 2, t = lane & 3;
    const int ar = wid * 16 + g;
    const int c2 = 2 * t;

    const uint32_t qs_a = smem_u32(Qs), ks_a = smem_u32(Ks);
    const uint32_t vt_a[2] = { smem_u32(VT0), smem_u32(VT1) };

#define FL_ISSUE(gptr, ldh, saddr) do {                                        \
        _Pragma("unroll")                                                      \
        for (int i_ = 0; i_ < 4; i_++) {                                       \
            const int idx_ = tid + i_ * 128;                                   \
            const int row_ = idx_ >> 3, gr_ = idx_ & 7;                        \
            CP_ASYNC16((saddr) + (uint32_t)(row_ * (FP * 4) + gr_ * 16),       \
                       (gptr) + (size_t)row_ * (ldh) + gr_ * 8);               \
        }                                                                      \
    } while (0)

    FL_ISSUE(Qg, QKV_LD, qs_a);
    FL_ISSUE(Kg, QKV_LD, ks_a);
    FL_ISSUE(Vtg, SEQ, vt_a[0]);
    CP_COMMIT();

    float m0 = -INFINITY, m1 = -INFINITY, l0 = 0.f, l1 = 0.f;
    float o[8][4];
#pragma unroll
    for (int nt = 0; nt < 8; nt++)
#pragma unroll
        for (int j = 0; j < 4; j++) o[nt][j] = 0.f;

    uint32_t qf[4][4];                      // Q fragments, loop-invariant

    const int NT = SEQ / BKV;               // 32 tiles
    for (int tile = 0; tile < NT; tile++) {
        const int jt = tile * BKV;
        CP_WAIT(0);
        __syncthreads();
        if (tid < BKV) msk[tid] = mask[(size_t)b * SEQ + jt + tid];

        if (tile == 0) {                    // hoisted Q fragment load
#pragma unroll
            for (int ks = 0; ks < 4; ks++) {
                const int kc = ks * 8 + t;
                qf[ks][0] = Qs[ar * FP + kc];
                qf[ks][1] = Qs[(ar + 8) * FP + kc];
                qf[ks][2] = Qs[ar * FP + kc + 4];
                qf[ks][3] = Qs[(ar + 8) * FP + kc + 4];
            }
        }

        // ---- S = Q @ K^T (q carries 0.125*log2e) ----
        float s[8][4];
#pragma unroll
        for (int nt = 0; nt < 8; nt++)
#pragma unroll
            for (int j = 0; j < 4; j++) s[nt][j] = 0.f;

#pragma unroll
        for (int ks = 0; ks < 4; ks++) {      // DK=64 -> 4 x k16
            const int kc = ks * 8 + t;
#pragma unroll
            for (int nt = 0; nt < 8; nt++) {
                const int rn = nt * 8 + g;
                uint32_t bb[2] = { Ks[rn * FP + kc], Ks[rn * FP + kc + 4] };
                mma_f16(s[nt], qf[ks], bb);
            }
        }
        __syncthreads();                      // Ks consumed + msk visible

        if (tile + 1 < NT) {
            FL_ISSUE(Kg + (size_t)(jt + BKV) * QKV_LD, QKV_LD, ks_a);
            FL_ISSUE(Vtg + (jt + BKV), SEQ, vt_a[(tile + 1) & 1]);
            CP_COMMIT();
        }

        // ---- mask ----
#pragma unroll
        for (int nt = 0; nt < 8; nt++) {
            const int c0 = nt * 8 + c2;
            if (msk[c0] == 0)     { s[nt][0] = -1e9f; s[nt][2] = -1e9f; }
            if (msk[c0 + 1] == 0) { s[nt][1] = -1e9f; s[nt][3] = -1e9f; }
        }

        // ---- online softmax (exp2 domain) ----
        float mx0 = -INFINITY, mx1 = -INFINITY;
#pragma unroll
        for (int nt = 0; nt < 8; nt++) {
            mx0 = fmaxf(mx0, fmaxf(s[nt][0], s[nt][1]));
            mx1 = fmaxf(mx1, fmaxf(s[nt][2], s[nt][3]));
        }
        mx0 = fmaxf(mx0, __shfl_xor_sync(0xffffffffu, mx0, 1));
        mx0 = fmaxf(mx0, __shfl_xor_sync(0xffffffffu, mx0, 2));
        mx1 = fmaxf(mx1, __shfl_xor_sync(0xffffffffu, mx1, 1));
        mx1 = fmaxf(mx1, __shfl_xor_sync(0xffffffffu, mx1, 2));

        const float mn0 = fmaxf(m0, mx0), mn1 = fmaxf(m1, mx1);
        const float sc0 = ex2(m0 - mn0), sc1 = ex2(m1 - mn1);

        float sum0 = 0.f, sum1 = 0.f;
#pragma unroll
        for (int nt = 0; nt < 8; nt++) {
            const float p0 = ex2(s[nt][0] - mn0);
            const float p1 = ex2(s[nt][1] - mn0);
            const float p2 = ex2(s[nt][2] - mn1);
            const float p3 = ex2(s[nt][3] - mn1);
            sum0 += p0 + p1; sum1 += p2 + p3;
            const int pc = nt * 4 + t;        // half2 word col
            Ps[ar * FP + pc]       = f22h2(p0, p1);
            Ps[(ar + 8) * FP + pc] = f22h2(p2, p3);
            o[nt][0] *= sc0; o[nt][1] *= sc0;
            o[nt][2] *= sc1; o[nt][3] *= sc1;
        }
        sum0 += __shfl_xor_sync(0xffffffffu, sum0, 1);
        sum0 += __shfl_xor_sync(0xffffffffu, sum0, 2);
        sum1 += __shfl_xor_sync(0xffffffffu, sum1, 1);
        sum1 += __shfl_xor_sync(0xffffffffu, sum1, 2);
        l0 = l0 * sc0 + sum0;
        l1 = l1 * sc1 + sum1;
        m0 = mn0; m1 = mn1;
        __syncwarp();                         // Ps rows warp-private

        // ---- O += P @ VT^T ----
        const uint32_t* Vc = (tile & 1) ? VT1 : VT0;
#pragma unroll
        for (int ks = 0; ks < 4; ks++) {      // j=64 -> 4 x k16
            const int kc = ks * 8 + t;
            uint32_t a[4];
            a[0] = Ps[ar * FP + kc];
            a[1] = Ps[(ar + 8) * FP + kc];
            a[2] = Ps[ar * FP + kc + 4];
            a[3] = Ps[(ar + 8) * FP + kc + 4];
#pragma unroll
            for (int nt = 0; nt < 8; nt++) {
                const int rn = nt * 8 + g;
                uint32_t bb[2] = { Vc[rn * FP + kc], Vc[rn * FP + kc + 4] };
                mma_f16(o[nt], a, bb);
            }
        }
    }
#undef FL_ISSUE

    const float inv0 = 1.f / l0, inv1 = 1.f / l1;
    __half* Og = out + ((size_t)(b * SEQ + qi0)) * DMODEL + h * DK;
#pragma unroll
    for (int nt = 0; nt < 8; nt++) {
        const int c0 = nt * 8 + c2;
        *(uint32_t*)&Og[(size_t)ar * DMODEL + c0] =
            f22h2(o[nt][0] * inv0, o[nt][1] * inv0);
        *(uint32_t*)&Og[(size_t)(ar + 8) * DMODEL + c0] =
            f22h2(o[nt][2] * inv1, o[nt][3] * inv1);
    }
}

// ---------------------------------------------------------------------------
// Launch sequence
// ---------------------------------------------------------------------------
extern "C" void kernel_launch(void* const* d_in, const int* in_sizes, int n_in,
                              void* d_out, int out_size)
{
    const float* x    = (const float*)d_in[0];
    const int*   mask = (const int*)  d_in[1];
    const float* wq   = (const float*)d_in[2];
    const float* bq   = (const float*)d_in[3];
    const float* wk   = (const float*)d_in[4];
    const float* bk   = (const float*)d_in[5];
    const float* wv   = (const float*)d_in[6];
    const float* bv   = (const float*)d_in[7];
    const float* wo   = (const float*)d_in[8];
    const float* bo   = (const float*)d_in[9];
    const float* w1   = (const float*)d_in[10];
    const float* b1   = (const float*)d_in[11];
    const float* w2   = (const float*)d_in[12];
    const float* b2   = (const float*)d_in[13];
    const float* a1   = (const float*)d_in[14];
    const float* n1   = (const float*)d_in[15];
    const float* a2   = (const float*)d_in[16];
    const float* n2   = (const float*)d_in[17];
    float* out = (float*)d_out;

    __half *xn, *qkv, *vT, *attn, *ff, *wqkv, *wo_h, *w1_h, *w2_h;
    float *x1, *bqkv;
    cudaGetSymbolAddress((void**)&xn,   g_xn);
    cudaGetSymbolAddress((void**)&qkv,  g_qkv);
    cudaGetSymbolAddress((void**)&vT,   g_vT);
    cudaGetSymbolAddress((void**)&attn, g_attn);
    cudaGetSymbolAddress((void**)&x1,   g_x1);
    cudaGetSymbolAddress((void**)&ff,   g_ff);
    cudaGetSymbolAddress((void**)&wqkv, g_wqkv);
    cudaGetSymbolAddress((void**)&wo_h, g_wo_h);
    cudaGetSymbolAddress((void**)&w1_h, g_w1_h);
    cudaGetSymbolAddress((void**)&w2_h, g_w2_h);
    cudaGetSymbolAddress((void**)&bqkv, g_bqkv);

    cudaFuncSetAttribute(gemm_mma<1>, cudaFuncAttributeMaxDynamicSharedMemorySize, GEMM_SMEM);
    cudaFuncSetAttribute(gemm_mma<2>, cudaFuncAttributeMaxDynamicSharedMemorySize, GEMM_SMEM);
    cudaFuncSetAttribute(gemm_mma<3>, cudaFuncAttributeMaxDynamicSharedMemorySize, GEMM_SMEM);
    cudaFuncSetAttribute(flash_attn,  cudaFuncAttributeMaxDynamicSharedMemorySize, FLASH_SMEM);

    // --- prep: one launch for all weight rounding + bias pack ---
    prep_all<<<PREP_GRID, 256>>>(wq, wk, wv, wo, w1, w2, bq, bk, bv,
                                 wqkv, wo_h, w1_h, w2_h, bqkv);

    // --- residual 1: pre-norm + attention ---
    ln_kernel<<<MTOK, 256>>>(x, xn, a1, n1);

    gemm_mma<3><<<dim3(QKV_LD / 128, MTOK / 128), 128, GEMM_SMEM>>>(
        xn, wqkv, bqkv, nullptr, qkv, nullptr, vT, DMODEL, DMODEL, DMODEL, QKV_LD);

    flash_attn<<<dim3(SEQ / BQ, BATCH * NHEAD), 128, FLASH_SMEM>>>(qkv, vT, mask, attn);

    gemm_mma<2><<<dim3(DMODEL / 128, MTOK / 128), 128, GEMM_SMEM>>>(
        attn, wo_h, bo, x, nullptr, x1, nullptr, DMODEL, DMODEL, DMODEL, DMODEL);

    // --- residual 2: pre-norm + FFN ---
    ln_kernel<<<MTOK, 256>>>(x1, xn, a2, n2);

    gemm_mma<1><<<dim3(DFF / 128, MTOK / 128), 128, GEMM_SMEM>>>(
        xn, w1_h, b1, nullptr, ff, nullptr, nullptr, DMODEL, DMODEL, DMODEL, DFF);

    gemm_mma<2><<<dim3(DMODEL / 128, MTOK / 128), 128, GEMM_SMEM>>>(
        ff, w2_h, b2, x1, nullptr, out, nullptr, DFF, DFF, DFF, DMODEL);
}